// round 2
// baseline (speedup 1.0000x reference)
#include <cuda_runtime.h>
#include <cuda_bf16.h>

#define NMAX 100000
#define EMAX 1600000
#define GMAX 1000
#define EPS 1e-5f

// ---- scratch (static device globals; no allocation) ----
__device__ float  g_deg [NMAX];
__device__ float  g_agg [NMAX * 32];
__device__ float  g_x1  [NMAX * 32];
__device__ float  g_x2  [NMAX * 32];
__device__ float  g_x3  [NMAX * 32];
__device__ float  g_x4  [NMAX];
__device__ float  g_hg  [GMAX * 129];
__device__ float  g_cnt [GMAX];
__device__ double g_sum  [32];
__device__ double g_sumsq[32];

// ---- in-degree: one atomic per edge ----
__global__ void deg_kernel(const int* __restrict__ dst, float* __restrict__ deg, int E) {
    int e = blockIdx.x * blockDim.x + threadIdx.x;
    if (e < E) atomicAdd(&deg[dst[e]], 1.0f);
}

// ---- mean-agg scatter: warp per edge, lane = channel ----
__global__ void scatter_kernel(const float* __restrict__ x, const int* __restrict__ src,
                               const int* __restrict__ dst, float* __restrict__ agg, int E) {
    int t = blockIdx.x * blockDim.x + threadIdx.x;
    int e = t >> 5, lane = t & 31;
    if (e >= E) return;
    int s = src[e];
    int d = dst[e];
    atomicAdd(&agg[d * 32 + lane], x[s * 32 + lane]);
}

// ---- fused (agg/deg) @ W + b ----
template <int OUT>
__global__ void linear_kernel(const float* __restrict__ agg, const float* __restrict__ deg,
                              const float* __restrict__ W, const float* __restrict__ b,
                              float* __restrict__ out, int n) {
    __shared__ float Ws[32 * OUT];
    __shared__ float bs[OUT];
    for (int i = threadIdx.x; i < 32 * OUT; i += blockDim.x) Ws[i] = W[i];
    if (threadIdx.x < OUT) bs[threadIdx.x] = b[threadIdx.x];
    __syncthreads();
    int v = blockIdx.x * blockDim.x + threadIdx.x;
    if (v >= n) return;
    float inv = 1.0f / fmaxf(deg[v], 1.0f);
    float x[32];
#pragma unroll
    for (int i = 0; i < 32; i++) x[i] = agg[v * 32 + i] * inv;
#pragma unroll
    for (int o = 0; o < OUT; o++) {
        float acc = bs[o];
#pragma unroll
        for (int i = 0; i < 32; i++) acc = fmaf(x[i], Ws[i * OUT + o], acc);
        out[v * OUT + o] = acc;
    }
}

// ---- per-channel sum / sumsq (double accumulators) ----
// Requires (gridDim.x*blockDim.x) % OUT == 0 so each thread owns one channel.
template <int OUT>
__global__ void stats_kernel(const float* __restrict__ lin, int n,
                             double* __restrict__ gsum, double* __restrict__ gsumsq) {
    __shared__ double ss[OUT], ss2[OUT];
    if (threadIdx.x < OUT) { ss[threadIdx.x] = 0.0; ss2[threadIdx.x] = 0.0; }
    __syncthreads();
    int total  = n * OUT;
    int stride = gridDim.x * blockDim.x;
    int tg     = blockIdx.x * blockDim.x + threadIdx.x;
    int c      = tg % OUT;
    double s = 0.0, s2 = 0.0;
    for (int j = tg; j < total; j += stride) {
        float x = lin[j];
        s  += (double)x;
        s2 += (double)x * (double)x;
    }
    atomicAdd(&ss[c], s);
    atomicAdd(&ss2[c], s2);
    __syncthreads();
    if (threadIdx.x < OUT) {
        atomicAdd(&gsum[threadIdx.x],   ss[threadIdx.x]);
        atomicAdd(&gsumsq[threadIdx.x], ss2[threadIdx.x]);
    }
}

// ---- in-place BN (batch stats) + ReLU ----
template <int OUT>
__global__ void bn_relu_kernel(float* __restrict__ x, int n,
                               const double* __restrict__ gsum, const double* __restrict__ gsumsq,
                               const float* __restrict__ gamma, const float* __restrict__ beta) {
    int j = blockIdx.x * blockDim.x + threadIdx.x;
    if (j >= n * OUT) return;
    int c = j % OUT;
    double m   = gsum[c] / (double)n;
    double var = gsumsq[c] / (double)n - m * m;
    float  rs  = rsqrtf((float)var + EPS);
    float  y   = gamma[c] * ((x[j] - (float)m) * rs) + beta[c];
    x[j] = fmaxf(y, 0.0f);
}

// ---- per-graph mean pool of concat [h | x1 | x2 | x3 | x4] : warp per node ----
__global__ void pool_kernel(const float* __restrict__ h,  const float* __restrict__ x1,
                            const float* __restrict__ x2, const float* __restrict__ x3,
                            const float* __restrict__ x4, const int* __restrict__ gid,
                            float* __restrict__ hg, float* __restrict__ cnt, int n) {
    int t = blockIdx.x * blockDim.x + threadIdx.x;
    int v = t >> 5, lane = t & 31;
    if (v >= n) return;
    int g = gid[v];
    float* row = hg + (size_t)g * 129;
    atomicAdd(&row[lane],      h [v * 32 + lane]);
    atomicAdd(&row[32 + lane], x1[v * 32 + lane]);
    atomicAdd(&row[64 + lane], x2[v * 32 + lane]);
    atomicAdd(&row[96 + lane], x3[v * 32 + lane]);
    if (lane == 0) {
        atomicAdd(&row[128], x4[v]);
        atomicAdd(&cnt[g], 1.0f);
    }
}

// ---- MLP head: block per graph, 128 threads ----
__global__ void mlp_kernel(const float* __restrict__ hgsum, const float* __restrict__ cnt,
                           const float* __restrict__ W0, const float* __restrict__ b0,
                           const float* __restrict__ W1, const float* __restrict__ b1,
                           const float* __restrict__ W2, const float* __restrict__ b2,
                           float* __restrict__ out) {
    int g = blockIdx.x;
    __shared__ float hr[129];
    __shared__ float l0[128];
    __shared__ float l1[64];
    float invc = 1.0f / fmaxf(cnt[g], 1.0f);
    for (int c = threadIdx.x; c < 129; c += blockDim.x) hr[c] = hgsum[(size_t)g * 129 + c] * invc;
    __syncthreads();
    int t = threadIdx.x;
    // layer 0: 129 -> 128
    {
        float acc = b0[t];
#pragma unroll 4
        for (int i = 0; i < 129; i++) acc = fmaf(hr[i], W0[i * 128 + t], acc);
        l0[t] = fmaxf(acc, 0.0f);
    }
    __syncthreads();
    // layer 1: 128 -> 64
    if (t < 64) {
        float acc = b1[t];
#pragma unroll 4
        for (int i = 0; i < 128; i++) acc = fmaf(l0[i], W1[i * 64 + t], acc);
        l1[t] = fmaxf(acc, 0.0f);
    }
    __syncthreads();
    // layer 2: 64 -> 1
    if (t == 0) {
        float acc = b2[0];
        for (int i = 0; i < 64; i++) acc = fmaf(l1[i], W2[i], acc);
        out[g] = acc;
    }
}

extern "C" void kernel_launch(void* const* d_in, const int* in_sizes, int n_in,
                              void* d_out, int out_size) {
    const float* h   = (const float*)d_in[0];
    const int*   src = (const int*)d_in[1];
    const int*   dst = (const int*)d_in[2];
    const int*   gid = (const int*)d_in[3];
    const int E = in_sizes[1];
    const int N = in_sizes[3];
    const int G = out_size;
    float* out = (float*)d_out;

    // conv/bn params: index 4 + 4*i : w, b, gamma, beta
    const float* cw[4]; const float* cb[4]; const float* bg[4]; const float* bb[4];
    for (int i = 0; i < 4; i++) {
        cw[i] = (const float*)d_in[4 + 4 * i + 0];
        cb[i] = (const float*)d_in[4 + 4 * i + 1];
        bg[i] = (const float*)d_in[4 + 4 * i + 2];
        bb[i] = (const float*)d_in[4 + 4 * i + 3];
    }
    const float* W0 = (const float*)d_in[20];
    const float* b0 = (const float*)d_in[21];
    const float* W1 = (const float*)d_in[22];
    const float* b1 = (const float*)d_in[23];
    const float* W2 = (const float*)d_in[24];
    const float* b2 = (const float*)d_in[25];

    float *deg, *agg, *x1, *x2, *x3, *x4, *hg, *cnt;
    double *sum, *sumsq;
    cudaGetSymbolAddress((void**)&deg,   g_deg);
    cudaGetSymbolAddress((void**)&agg,   g_agg);
    cudaGetSymbolAddress((void**)&x1,    g_x1);
    cudaGetSymbolAddress((void**)&x2,    g_x2);
    cudaGetSymbolAddress((void**)&x3,    g_x3);
    cudaGetSymbolAddress((void**)&x4,    g_x4);
    cudaGetSymbolAddress((void**)&hg,    g_hg);
    cudaGetSymbolAddress((void**)&cnt,   g_cnt);
    cudaGetSymbolAddress((void**)&sum,   g_sum);
    cudaGetSymbolAddress((void**)&sumsq, g_sumsq);

    const int T = 256;
    // init
    cudaMemsetAsync(deg, 0, (size_t)N * sizeof(float));
    cudaMemsetAsync(hg,  0, (size_t)G * 129 * sizeof(float));
    cudaMemsetAsync(cnt, 0, (size_t)G * sizeof(float));
    deg_kernel<<<(E + T - 1) / T, T>>>(dst, deg, E);

    const float* xin = h;
    float* xout[4] = {x1, x2, x3, x4};

    // layers 0..2 (32 -> 32)
    for (int i = 0; i < 3; i++) {
        cudaMemsetAsync(agg,   0, (size_t)N * 32 * sizeof(float));
        cudaMemsetAsync(sum,   0, 32 * sizeof(double));
        cudaMemsetAsync(sumsq, 0, 32 * sizeof(double));
        scatter_kernel<<<((size_t)E * 32 + T - 1) / T, T>>>(xin, src, dst, agg, E);
        linear_kernel<32><<<(N + T - 1) / T, T>>>(agg, deg, cw[i], cb[i], xout[i], N);
        stats_kernel<32><<<296, T>>>(xout[i], N, sum, sumsq);
        bn_relu_kernel<32><<<(N * 32 + T - 1) / T, T>>>(xout[i], N, sum, sumsq, bg[i], bb[i]);
        xin = xout[i];
    }
    // layer 3 (32 -> 1)
    {
        cudaMemsetAsync(agg,   0, (size_t)N * 32 * sizeof(float));
        cudaMemsetAsync(sum,   0, 32 * sizeof(double));
        cudaMemsetAsync(sumsq, 0, 32 * sizeof(double));
        scatter_kernel<<<((size_t)E * 32 + T - 1) / T, T>>>(xin, src, dst, agg, E);
        linear_kernel<1><<<(N + T - 1) / T, T>>>(agg, deg, cw[3], cb[3], x4, N);
        stats_kernel<1><<<296, T>>>(x4, N, sum, sumsq);
        bn_relu_kernel<1><<<(N + T - 1) / T, T>>>(x4, N, sum, sumsq, bg[3], bb[3]);
    }

    // pool + MLP
    pool_kernel<<<((size_t)N * 32 + T - 1) / T, T>>>(h, x1, x2, x3, x4, gid, hg, cnt, N);
    mlp_kernel<<<G, 128>>>(hg, cnt, W0, b0, W1, b1, W2, b2, out);
}

// round 3
// speedup vs baseline: 1.2689x; 1.2689x over previous
#include <cuda_runtime.h>
#include <cuda_bf16.h>

#define NMAX 100000
#define EMAX 1600000
#define GMAX 1000
#define EPS 1e-5f

// ---- scratch (static device globals; no allocation) ----
__device__ int    g_hist[NMAX];
__device__ int    g_rp  [NMAX + 1];   // CSR row ptr (by dst)
__device__ int    g_pos [NMAX];       // fill cursor
__device__ int    g_ci  [EMAX];       // CSR col idx (src)
__device__ int    g_gp  [GMAX + 1];   // per-graph node ranges
__device__ float  g_x1  [NMAX * 32];
__device__ float  g_x2  [NMAX * 32];
__device__ float  g_x3  [NMAX * 32];
__device__ float  g_x4  [NMAX];
__device__ double g_sum  [32];
__device__ double g_sumsq[32];

// ---- histogram of dst ----
__global__ void hist_kernel(const int* __restrict__ dst, int* __restrict__ hist, int E) {
    int e = blockIdx.x * blockDim.x + threadIdx.x;
    if (e < E) atomicAdd(&hist[dst[e]], 1);
}

// ---- single-block exclusive scan (n up to ~100k), out has n+1 entries ----
__global__ void scan_kernel(const int* __restrict__ in, int* __restrict__ out, int n) {
    __shared__ int part[1024];
    const int T = 1024;
    int t = threadIdx.x;
    int chunk = (n + T - 1) / T;
    int begin = t * chunk;
    int end   = min(begin + chunk, n);
    int s = 0;
    for (int i = begin; i < end; i++) s += in[i];
    part[t] = s;
    __syncthreads();
    for (int off = 1; off < T; off <<= 1) {
        int v = (t >= off) ? part[t - off] : 0;
        __syncthreads();
        part[t] += v;
        __syncthreads();
    }
    int prefix = (t == 0) ? 0 : part[t - 1];
    for (int i = begin; i < end; i++) { int v = in[i]; out[i] = prefix; prefix += v; }
    if (t == T - 1) out[n] = prefix;
}

// ---- fill CSR: slot per edge via atomic cursor ----
__global__ void fill_kernel(const int* __restrict__ src, const int* __restrict__ dst,
                            int* __restrict__ pos, int* __restrict__ ci, int E) {
    int e = blockIdx.x * blockDim.x + threadIdx.x;
    if (e < E) {
        int slot = atomicAdd(&pos[dst[e]], 1);
        ci[slot] = src[e];
    }
}

// ---- graph ranges: gid is sorted; binary search first index >= g ----
__global__ void graph_ptr_kernel(const int* __restrict__ gid, int* __restrict__ gp, int n, int G) {
    int g = blockIdx.x * blockDim.x + threadIdx.x;
    if (g > G) return;
    int lo = 0, hi = n;
    while (lo < hi) { int mid = (lo + hi) >> 1; if (gid[mid] < g) lo = mid + 1; else hi = mid; }
    gp[g] = lo;
}

// ---- fused: CSR mean-gather + linear(32->OUT) + BN-stat accumulation ----
// block = 256 threads = 8 warps, warp per node, lane = channel
template <int OUT>
__global__ void gcn_layer_kernel(const float* __restrict__ x, const int* __restrict__ rp,
                                 const int* __restrict__ ci, const float* __restrict__ W,
                                 const float* __restrict__ b, float* __restrict__ out, int n,
                                 double* __restrict__ gsum, double* __restrict__ gsumsq) {
    __shared__ float  Ws[32 * OUT];
    __shared__ float  bs[OUT];
    __shared__ float  xv[8][32];
    __shared__ double ssum[OUT], ssq[OUT];
    for (int i = threadIdx.x; i < 32 * OUT; i += 256) Ws[i] = W[i];
    if (threadIdx.x < OUT) {
        bs[threadIdx.x]   = b[threadIdx.x];
        ssum[threadIdx.x] = 0.0;
        ssq[threadIdx.x]  = 0.0;
    }
    __syncthreads();
    int w = threadIdx.x >> 5, lane = threadIdx.x & 31;
    int v = blockIdx.x * 8 + w;
    if (v < n) {
        int beg = rp[v], end = rp[v + 1];
        float a0 = 0.f, a1 = 0.f, a2 = 0.f, a3 = 0.f;
        int j = beg;
        for (; j + 3 < end; j += 4) {
            int s0 = ci[j], s1 = ci[j + 1], s2 = ci[j + 2], s3 = ci[j + 3];
            a0 += x[s0 * 32 + lane];
            a1 += x[s1 * 32 + lane];
            a2 += x[s2 * 32 + lane];
            a3 += x[s3 * 32 + lane];
        }
        for (; j < end; j++) a0 += x[ci[j] * 32 + lane];
        float acc = (a0 + a1) + (a2 + a3);
        float inv = 1.0f / fmaxf((float)(end - beg), 1.0f);
        float xl  = acc * inv;
        if constexpr (OUT == 32) {
            xv[w][lane] = xl;
            __syncwarp();
            float o = bs[lane];
#pragma unroll
            for (int i = 0; i < 32; i++) o = fmaf(xv[w][i], Ws[i * 32 + lane], o);
            out[v * 32 + lane] = o;
            atomicAdd(&ssum[lane], (double)o);
            atomicAdd(&ssq[lane],  (double)o * (double)o);
        } else {
            float p = xl * Ws[lane];
#pragma unroll
            for (int off = 16; off; off >>= 1) p += __shfl_down_sync(0xffffffffu, p, off);
            if (lane == 0) {
                float o = p + bs[0];
                out[v] = o;
                atomicAdd(&ssum[0], (double)o);
                atomicAdd(&ssq[0],  (double)o * (double)o);
            }
        }
    }
    __syncthreads();
    if (threadIdx.x < OUT) {
        atomicAdd(&gsum[threadIdx.x],   ssum[threadIdx.x]);
        atomicAdd(&gsumsq[threadIdx.x], ssq[threadIdx.x]);
    }
}

// ---- in-place BN (batch stats) + ReLU ----
template <int OUT>
__global__ void bn_relu_kernel(float* __restrict__ x, int n,
                               const double* __restrict__ gsum, const double* __restrict__ gsumsq,
                               const float* __restrict__ gamma, const float* __restrict__ beta) {
    int j = blockIdx.x * blockDim.x + threadIdx.x;
    if (j >= n * OUT) return;
    int c = (OUT == 1) ? 0 : (j & 31);
    double m   = gsum[c] / (double)n;
    double var = gsumsq[c] / (double)n - m * m;
    float  rs  = rsqrtf((float)var + EPS);
    float  y   = gamma[c] * ((x[j] - (float)m) * rs) + beta[c];
    x[j] = fmaxf(y, 0.0f);
}

// ---- fused per-graph mean pool (atomic-free; gid sorted) + MLP head ----
// block per graph, 128 threads
__global__ void pool_mlp_kernel(const float* __restrict__ h,  const float* __restrict__ x1,
                                const float* __restrict__ x2, const float* __restrict__ x3,
                                const float* __restrict__ x4, const int* __restrict__ gp,
                                const float* __restrict__ W0, const float* __restrict__ b0,
                                const float* __restrict__ W1, const float* __restrict__ b1,
                                const float* __restrict__ W2, const float* __restrict__ b2,
                                float* __restrict__ out) {
    int g = blockIdx.x;
    int beg = gp[g], end = gp[g + 1];
    int t = threadIdx.x;
    __shared__ float hr[129];
    __shared__ float l0[128];
    __shared__ float l1[64];
    float inv = 1.0f / fmaxf((float)(end - beg), 1.0f);
    {
        int c = t & 31;
        int w = t >> 5;
        const float* p = (w == 0) ? h : (w == 1) ? x1 : (w == 2) ? x2 : x3;
        float s = 0.f;
        for (int v = beg; v < end; v++) s += p[v * 32 + c];
        hr[t] = s * inv;
    }
    if (t == 0) {
        float s = 0.f;
        for (int v = beg; v < end; v++) s += x4[v];
        hr[128] = s * inv;
    }
    __syncthreads();
    // layer 0: 129 -> 128
    {
        float acc = b0[t];
#pragma unroll 4
        for (int i = 0; i < 129; i++) acc = fmaf(hr[i], W0[i * 128 + t], acc);
        l0[t] = fmaxf(acc, 0.0f);
    }
    __syncthreads();
    // layer 1: 128 -> 64
    if (t < 64) {
        float acc = b1[t];
#pragma unroll 4
        for (int i = 0; i < 128; i++) acc = fmaf(l0[i], W1[i * 64 + t], acc);
        l1[t] = fmaxf(acc, 0.0f);
    }
    __syncthreads();
    // layer 2: 64 -> 1
    if (t == 0) {
        float acc = b2[0];
        for (int i = 0; i < 64; i++) acc = fmaf(l1[i], W2[i], acc);
        out[g] = acc;
    }
}

extern "C" void kernel_launch(void* const* d_in, const int* in_sizes, int n_in,
                              void* d_out, int out_size) {
    const float* h   = (const float*)d_in[0];
    const int*   src = (const int*)d_in[1];
    const int*   dst = (const int*)d_in[2];
    const int*   gid = (const int*)d_in[3];
    const int E = in_sizes[1];
    const int N = in_sizes[3];
    const int G = out_size;
    float* out = (float*)d_out;

    const float* cw[4]; const float* cb[4]; const float* bg[4]; const float* bb[4];
    for (int i = 0; i < 4; i++) {
        cw[i] = (const float*)d_in[4 + 4 * i + 0];
        cb[i] = (const float*)d_in[4 + 4 * i + 1];
        bg[i] = (const float*)d_in[4 + 4 * i + 2];
        bb[i] = (const float*)d_in[4 + 4 * i + 3];
    }
    const float* W0 = (const float*)d_in[20];
    const float* b0 = (const float*)d_in[21];
    const float* W1 = (const float*)d_in[22];
    const float* b1 = (const float*)d_in[23];
    const float* W2 = (const float*)d_in[24];
    const float* b2 = (const float*)d_in[25];

    int *hist, *rp, *pos, *ci, *gp;
    float *x1, *x2, *x3, *x4;
    double *sum, *sumsq;
    cudaGetSymbolAddress((void**)&hist,  g_hist);
    cudaGetSymbolAddress((void**)&rp,    g_rp);
    cudaGetSymbolAddress((void**)&pos,   g_pos);
    cudaGetSymbolAddress((void**)&ci,    g_ci);
    cudaGetSymbolAddress((void**)&gp,    g_gp);
    cudaGetSymbolAddress((void**)&x1,    g_x1);
    cudaGetSymbolAddress((void**)&x2,    g_x2);
    cudaGetSymbolAddress((void**)&x3,    g_x3);
    cudaGetSymbolAddress((void**)&x4,    g_x4);
    cudaGetSymbolAddress((void**)&sum,   g_sum);
    cudaGetSymbolAddress((void**)&sumsq, g_sumsq);

    const int T = 256;

    // ---- CSR build (once per launch) ----
    cudaMemsetAsync(hist, 0, (size_t)N * sizeof(int));
    hist_kernel<<<(E + T - 1) / T, T>>>(dst, hist, E);
    scan_kernel<<<1, 1024>>>(hist, rp, N);
    cudaMemcpyAsync(pos, rp, (size_t)N * sizeof(int), cudaMemcpyDeviceToDevice);
    fill_kernel<<<(E + T - 1) / T, T>>>(src, dst, pos, ci, E);
    graph_ptr_kernel<<<(G + 1 + T - 1) / T, T>>>(gid, gp, N, G);

    const float* xin = h;
    float* xout[3] = {x1, x2, x3};
    int nwb = (N + 7) / 8;  // warp-per-node blocks

    // layers 0..2 (32 -> 32)
    for (int i = 0; i < 3; i++) {
        cudaMemsetAsync(sum,   0, 32 * sizeof(double));
        cudaMemsetAsync(sumsq, 0, 32 * sizeof(double));
        gcn_layer_kernel<32><<<nwb, T>>>(xin, rp, ci, cw[i], cb[i], xout[i], N, sum, sumsq);
        bn_relu_kernel<32><<<(N * 32 + T - 1) / T, T>>>(xout[i], N, sum, sumsq, bg[i], bb[i]);
        xin = xout[i];
    }
    // layer 3 (32 -> 1)
    {
        cudaMemsetAsync(sum,   0, 32 * sizeof(double));
        cudaMemsetAsync(sumsq, 0, 32 * sizeof(double));
        gcn_layer_kernel<1><<<nwb, T>>>(xin, rp, ci, cw[3], cb[3], x4, N, sum, sumsq);
        bn_relu_kernel<1><<<(N + T - 1) / T, T>>>(x4, N, sum, sumsq, bg[3], bb[3]);
    }

    // fused pool + MLP
    pool_mlp_kernel<<<G, 128>>>(h, x1, x2, x3, x4, gp, W0, b0, W1, b1, W2, b2, out);
}

// round 4
// speedup vs baseline: 3.1961x; 2.5188x over previous
#include <cuda_runtime.h>
#include <cuda_bf16.h>

#define NMAX 100000
#define EMAX 1600000
#define GMAX 1000
#define EPS 1e-5f

// ---- scratch (static device globals; no allocation) ----
__device__ int    g_hist[NMAX];
__device__ int    g_rp  [NMAX + 1];   // CSR row ptr (by dst)
__device__ int    g_pos [NMAX];       // fill cursor
__device__ int    g_ci  [EMAX];       // CSR col idx (src)
__device__ int    g_gp  [GMAX + 1];   // per-graph node ranges
__device__ float  g_x1  [NMAX * 32];  // raw linear outputs (pre-BN)
__device__ float  g_x2  [NMAX * 32];
__device__ float  g_x3  [NMAX * 32];
__device__ float  g_x4  [NMAX];
__device__ double g_stats[4 * 64];    // per layer: [0..31]=sum, [32..63]=sumsq

// ---- histogram of dst ----
__global__ void hist_kernel(const int* __restrict__ dst, int* __restrict__ hist, int E) {
    int e = blockIdx.x * blockDim.x + threadIdx.x;
    if (e < E) atomicAdd(&hist[dst[e]], 1);
}

// ---- single-block exclusive scan, out has n+1 entries ----
__global__ void scan_kernel(const int* __restrict__ in, int* __restrict__ out, int n) {
    __shared__ int part[1024];
    const int T = 1024;
    int t = threadIdx.x;
    int chunk = (n + T - 1) / T;
    int begin = t * chunk;
    int end   = min(begin + chunk, n);
    int s = 0;
    for (int i = begin; i < end; i++) s += in[i];
    part[t] = s;
    __syncthreads();
    for (int off = 1; off < T; off <<= 1) {
        int v = (t >= off) ? part[t - off] : 0;
        __syncthreads();
        part[t] += v;
        __syncthreads();
    }
    int prefix = (t == 0) ? 0 : part[t - 1];
    for (int i = begin; i < end; i++) { int v = in[i]; out[i] = prefix; prefix += v; }
    if (t == T - 1) out[n] = prefix;
}

// ---- fill CSR: slot per edge via atomic cursor ----
__global__ void fill_kernel(const int* __restrict__ src, const int* __restrict__ dst,
                            int* __restrict__ pos, int* __restrict__ ci, int E) {
    int e = blockIdx.x * blockDim.x + threadIdx.x;
    if (e < E) {
        int slot = atomicAdd(&pos[dst[e]], 1);
        ci[slot] = src[e];
    }
}

// ---- graph ranges via boundary scatter (gid sorted); O(1) work per thread ----
__global__ void graph_ptr_kernel(const int* __restrict__ gid, int* __restrict__ gp, int n, int G) {
    int v = blockIdx.x * blockDim.x + threadIdx.x;
    if (v > n) return;
    int g0 = (v == 0) ? -1 : gid[v - 1];
    int g1 = (v == n) ? G  : gid[v];
    for (int g = g0 + 1; g <= g1; g++) gp[g] = v;
}

// ---- fused: [BN+ReLU of input] + CSR mean-gather + linear(32->OUT) + stats ----
// persistent grid-stride, warp per node, lane = channel, 8-deep load pipeline
template <int OUT, bool BN>
__global__ void __launch_bounds__(512, 2)
gcn_layer_kernel(const float* __restrict__ x, const int* __restrict__ rp,
                 const int* __restrict__ ci, const float* __restrict__ W,
                 const float* __restrict__ bias,
                 const double* __restrict__ statsIn,
                 const float* __restrict__ gIn, const float* __restrict__ bIn,
                 float* __restrict__ out, int n, double* __restrict__ statsOut) {
    __shared__ float  Ws[32 * OUT];
    __shared__ float  bs[OUT];
    __shared__ float  As[32], Bs[32];
    __shared__ float  xv[16][33];
    __shared__ double ssum[32], ssq[32];
    int t = threadIdx.x;
    for (int i = t; i < 32 * OUT; i += 512) Ws[i] = W[i];
    if (t < OUT) bs[t] = bias[t];
    if (t < 32) {
        ssum[t] = 0.0; ssq[t] = 0.0;
        if (BN) {
            double m   = statsIn[t] / (double)n;
            double var = statsIn[32 + t] / (double)n - m * m;
            float  rs  = rsqrtf((float)var + EPS);
            float  A   = gIn[t] * rs;
            As[t] = A;
            Bs[t] = bIn[t] - (float)m * A;
        }
    }
    __syncthreads();
    int w = t >> 5, lane = t & 31;
    int warpsTotal = gridDim.x * 16;
    int wg = blockIdx.x * 16 + w;
    float A = BN ? As[lane] : 1.0f;
    float B = BN ? Bs[lane] : 0.0f;
    double tsum = 0.0, tsq = 0.0;
    for (int v = wg; v < n; v += warpsTotal) {
        int beg = rp[v], end = rp[v + 1];
        float acc = 0.f;
        int j = beg;
        for (; j + 8 <= end; j += 8) {
            int s0 = ci[j],     s1 = ci[j + 1], s2 = ci[j + 2], s3 = ci[j + 3];
            int s4 = ci[j + 4], s5 = ci[j + 5], s6 = ci[j + 6], s7 = ci[j + 7];
            float v0 = x[s0 * 32 + lane], v1 = x[s1 * 32 + lane];
            float v2 = x[s2 * 32 + lane], v3 = x[s3 * 32 + lane];
            float v4 = x[s4 * 32 + lane], v5 = x[s5 * 32 + lane];
            float v6 = x[s6 * 32 + lane], v7 = x[s7 * 32 + lane];
            if (BN) {
                v0 = fmaxf(fmaf(A, v0, B), 0.f); v1 = fmaxf(fmaf(A, v1, B), 0.f);
                v2 = fmaxf(fmaf(A, v2, B), 0.f); v3 = fmaxf(fmaf(A, v3, B), 0.f);
                v4 = fmaxf(fmaf(A, v4, B), 0.f); v5 = fmaxf(fmaf(A, v5, B), 0.f);
                v6 = fmaxf(fmaf(A, v6, B), 0.f); v7 = fmaxf(fmaf(A, v7, B), 0.f);
            }
            acc += ((v0 + v1) + (v2 + v3)) + ((v4 + v5) + (v6 + v7));
        }
        for (; j < end; j++) {
            float vv = x[ci[j] * 32 + lane];
            if (BN) vv = fmaxf(fmaf(A, vv, B), 0.f);
            acc += vv;
        }
        float xl = acc / fmaxf((float)(end - beg), 1.0f);
        if constexpr (OUT == 32) {
            xv[w][lane] = xl;
            __syncwarp();
            float o = bs[lane];
#pragma unroll
            for (int i = 0; i < 32; i++) o = fmaf(xv[w][i], Ws[i * 32 + lane], o);
            __syncwarp();
            out[v * 32 + lane] = o;
            tsum += (double)o;
            tsq  += (double)o * (double)o;
        } else {
            float p = xl * Ws[lane];
#pragma unroll
            for (int off = 16; off; off >>= 1) p += __shfl_down_sync(0xffffffffu, p, off);
            if (lane == 0) {
                float o = p + bs[0];
                out[v] = o;
                tsum += (double)o;
                tsq  += (double)o * (double)o;
            }
        }
    }
    if (OUT == 32 || lane == 0) {
        int c = (OUT == 32) ? lane : 0;
        atomicAdd(&ssum[c], tsum);
        atomicAdd(&ssq[c],  tsq);
    }
    __syncthreads();
    if (t < 32) {
        atomicAdd(&statsOut[t],      ssum[t]);
        atomicAdd(&statsOut[32 + t], ssq[t]);
    }
}

// ---- fused per-graph mean pool (BN applied on the fly) + MLP head ----
__global__ void pool_mlp_kernel(const float* __restrict__ h,  const float* __restrict__ x1,
                                const float* __restrict__ x2, const float* __restrict__ x3,
                                const float* __restrict__ x4, const int* __restrict__ gp,
                                const double* __restrict__ stats,
                                const float* __restrict__ g0, const float* __restrict__ be0,
                                const float* __restrict__ g1, const float* __restrict__ be1,
                                const float* __restrict__ g2, const float* __restrict__ be2,
                                const float* __restrict__ g3, const float* __restrict__ be3,
                                const float* __restrict__ W0, const float* __restrict__ b0,
                                const float* __restrict__ W1, const float* __restrict__ b1,
                                const float* __restrict__ W2, const float* __restrict__ b2,
                                float* __restrict__ out, int n) {
    __shared__ float As[97], Bs[97];
    __shared__ float hr[129];
    __shared__ float l0[128];
    __shared__ float l1[64];
    int t = threadIdx.x;
    if (t < 97) {
        int layer = (t < 96) ? (t >> 5) : 3;
        int c     = (t < 96) ? (t & 31) : 0;
        const double* st = stats + layer * 64;
        const float* gg = (layer == 0) ? g0 : (layer == 1) ? g1 : (layer == 2) ? g2 : g3;
        const float* bb = (layer == 0) ? be0 : (layer == 1) ? be1 : (layer == 2) ? be2 : be3;
        double m   = st[c] / (double)n;
        double var = st[32 + c] / (double)n - m * m;
        float  rs  = rsqrtf((float)var + EPS);
        float  A   = gg[c] * rs;
        As[t] = A;
        Bs[t] = bb[c] - (float)m * A;
    }
    __syncthreads();
    int g = blockIdx.x;
    int beg = gp[g], end = gp[g + 1];
    float inv = 1.0f / fmaxf((float)(end - beg), 1.0f);
    int w = t >> 5, c = t & 31;
    {
        const float* p = (w == 0) ? h : (w == 1) ? x1 : (w == 2) ? x2 : x3;
        float s = 0.f;
        if (w == 0) {
            int v = beg;
            for (; v + 4 <= end; v += 4) {
                float a = p[v * 32 + c],       b = p[(v + 1) * 32 + c];
                float d = p[(v + 2) * 32 + c], e = p[(v + 3) * 32 + c];
                s += (a + b) + (d + e);
            }
            for (; v < end; v++) s += p[v * 32 + c];
        } else {
            float A = As[(w - 1) * 32 + c];
            float B = Bs[(w - 1) * 32 + c];
            int v = beg;
            for (; v + 4 <= end; v += 4) {
                float a = p[v * 32 + c],       b = p[(v + 1) * 32 + c];
                float d = p[(v + 2) * 32 + c], e = p[(v + 3) * 32 + c];
                a = fmaxf(fmaf(A, a, B), 0.f); b = fmaxf(fmaf(A, b, B), 0.f);
                d = fmaxf(fmaf(A, d, B), 0.f); e = fmaxf(fmaf(A, e, B), 0.f);
                s += (a + b) + (d + e);
            }
            for (; v < end; v++) s += fmaxf(fmaf(A, p[v * 32 + c], B), 0.f);
        }
        hr[t] = s * inv;
    }
    if (t == 0) {
        float A = As[96], B = Bs[96];
        float s = 0.f;
        int v = beg;
        for (; v + 4 <= end; v += 4) {
            float a = fmaxf(fmaf(A, x4[v], B), 0.f);
            float b = fmaxf(fmaf(A, x4[v + 1], B), 0.f);
            float d = fmaxf(fmaf(A, x4[v + 2], B), 0.f);
            float e = fmaxf(fmaf(A, x4[v + 3], B), 0.f);
            s += (a + b) + (d + e);
        }
        for (; v < end; v++) s += fmaxf(fmaf(A, x4[v], B), 0.f);
        hr[128] = s * inv;
    }
    __syncthreads();
    // layer 0: 129 -> 128
    {
        float acc = b0[t];
#pragma unroll 4
        for (int i = 0; i < 129; i++) acc = fmaf(hr[i], W0[i * 128 + t], acc);
        l0[t] = fmaxf(acc, 0.0f);
    }
    __syncthreads();
    // layer 1: 128 -> 64
    if (t < 64) {
        float acc = b1[t];
#pragma unroll 4
        for (int i = 0; i < 128; i++) acc = fmaf(l0[i], W1[i * 64 + t], acc);
        l1[t] = fmaxf(acc, 0.0f);
    }
    __syncthreads();
    // layer 2: 64 -> 1
    if (t == 0) {
        float acc = b2[0];
        for (int i = 0; i < 64; i++) acc = fmaf(l1[i], W2[i], acc);
        out[g] = acc;
    }
}

extern "C" void kernel_launch(void* const* d_in, const int* in_sizes, int n_in,
                              void* d_out, int out_size) {
    const float* h   = (const float*)d_in[0];
    const int*   src = (const int*)d_in[1];
    const int*   dst = (const int*)d_in[2];
    const int*   gid = (const int*)d_in[3];
    const int E = in_sizes[1];
    const int N = in_sizes[3];
    const int G = out_size;
    float* out = (float*)d_out;

    const float* cw[4]; const float* cb[4]; const float* bg[4]; const float* bb[4];
    for (int i = 0; i < 4; i++) {
        cw[i] = (const float*)d_in[4 + 4 * i + 0];
        cb[i] = (const float*)d_in[4 + 4 * i + 1];
        bg[i] = (const float*)d_in[4 + 4 * i + 2];
        bb[i] = (const float*)d_in[4 + 4 * i + 3];
    }
    const float* W0 = (const float*)d_in[20];
    const float* b0 = (const float*)d_in[21];
    const float* W1 = (const float*)d_in[22];
    const float* b1 = (const float*)d_in[23];
    const float* W2 = (const float*)d_in[24];
    const float* b2 = (const float*)d_in[25];

    int *hist, *rp, *pos, *ci, *gp;
    float *x1, *x2, *x3, *x4;
    double *stats;
    cudaGetSymbolAddress((void**)&hist,  g_hist);
    cudaGetSymbolAddress((void**)&rp,    g_rp);
    cudaGetSymbolAddress((void**)&pos,   g_pos);
    cudaGetSymbolAddress((void**)&ci,    g_ci);
    cudaGetSymbolAddress((void**)&gp,    g_gp);
    cudaGetSymbolAddress((void**)&x1,    g_x1);
    cudaGetSymbolAddress((void**)&x2,    g_x2);
    cudaGetSymbolAddress((void**)&x3,    g_x3);
    cudaGetSymbolAddress((void**)&x4,    g_x4);
    cudaGetSymbolAddress((void**)&stats, g_stats);

    const int T = 256;

    // ---- CSR build + init ----
    cudaMemsetAsync(hist,  0, (size_t)N * sizeof(int));
    cudaMemsetAsync(stats, 0, 4 * 64 * sizeof(double));
    hist_kernel<<<(E + T - 1) / T, T>>>(dst, hist, E);
    scan_kernel<<<1, 1024>>>(hist, rp, N);
    cudaMemcpyAsync(pos, rp, (size_t)N * sizeof(int), cudaMemcpyDeviceToDevice);
    fill_kernel<<<(E + T - 1) / T, T>>>(src, dst, pos, ci, E);
    graph_ptr_kernel<<<(N + 1 + T - 1) / T, T>>>(gid, gp, N, G);

    // ---- GCN layers (persistent grid, 296 blocks x 512 threads) ----
    const int LG = 296, LT = 512;
    gcn_layer_kernel<32, false><<<LG, LT>>>(h,  rp, ci, cw[0], cb[0],
                                            nullptr, nullptr, nullptr,
                                            x1, N, stats + 0 * 64);
    gcn_layer_kernel<32, true><<<LG, LT>>>(x1, rp, ci, cw[1], cb[1],
                                           stats + 0 * 64, bg[0], bb[0],
                                           x2, N, stats + 1 * 64);
    gcn_layer_kernel<32, true><<<LG, LT>>>(x2, rp, ci, cw[2], cb[2],
                                           stats + 1 * 64, bg[1], bb[1],
                                           x3, N, stats + 2 * 64);
    gcn_layer_kernel<1, true><<<LG, LT>>>(x3, rp, ci, cw[3], cb[3],
                                          stats + 2 * 64, bg[2], bb[2],
                                          x4, N, stats + 3 * 64);

    // ---- fused pool + MLP ----
    pool_mlp_kernel<<<G, 128>>>(h, x1, x2, x3, x4, gp, stats,
                                bg[0], bb[0], bg[1], bb[1], bg[2], bb[2], bg[3], bb[3],
                                W0, b0, W1, b1, W2, b2, out, N);
}

// round 5
// speedup vs baseline: 3.4962x; 1.0939x over previous
#include <cuda_runtime.h>
#include <cuda_bf16.h>

#define NMAX 100000
#define EMAX 1600000
#define GMAX 1000
#define EPS 1e-5f

// ---- scratch (static device globals; no allocation) ----
__device__ int    g_hist[NMAX];
__device__ int    g_rp  [NMAX + 1];   // CSR row ptr (by dst)
__device__ int    g_pos [NMAX];       // fill cursor
__device__ int    g_ci  [EMAX];       // CSR col idx (src)
__device__ int    g_gp  [GMAX + 1];   // per-graph node ranges
__device__ float  g_x1  [NMAX * 32];  // raw linear outputs (pre-BN)
__device__ float  g_x2  [NMAX * 32];
__device__ float  g_x3  [NMAX * 32];
__device__ float  g_x4  [NMAX];
__device__ float  g_z   [NMAX];       // folded BN(x3)·W3
__device__ double g_stats[4 * 64];    // per layer: [0..31]=sum, [32..63]=sumsq

// ---- histogram of dst ----
__global__ void hist_kernel(const int* __restrict__ dst, int* __restrict__ hist, int E) {
    int e = blockIdx.x * blockDim.x + threadIdx.x;
    if (e < E) atomicAdd(&hist[dst[e]], 1);
}

// ---- single-block exclusive scan, out has n+1 entries ----
__global__ void scan_kernel(const int* __restrict__ in, int* __restrict__ out, int n) {
    __shared__ int part[1024];
    const int T = 1024;
    int t = threadIdx.x;
    int chunk = (n + T - 1) / T;
    int begin = t * chunk;
    int end   = min(begin + chunk, n);
    int s = 0;
    for (int i = begin; i < end; i++) s += in[i];
    part[t] = s;
    __syncthreads();
    for (int off = 1; off < T; off <<= 1) {
        int v = (t >= off) ? part[t - off] : 0;
        __syncthreads();
        part[t] += v;
        __syncthreads();
    }
    int prefix = (t == 0) ? 0 : part[t - 1];
    for (int i = begin; i < end; i++) { int v = in[i]; out[i] = prefix; prefix += v; }
    if (t == T - 1) out[n] = prefix;
}

// ---- fill CSR: slot per edge via atomic cursor ----
__global__ void fill_kernel(const int* __restrict__ src, const int* __restrict__ dst,
                            int* __restrict__ pos, int* __restrict__ ci, int E) {
    int e = blockIdx.x * blockDim.x + threadIdx.x;
    if (e < E) {
        int slot = atomicAdd(&pos[dst[e]], 1);
        ci[slot] = src[e];
    }
}

// ---- graph ranges via boundary scatter (gid sorted) ----
__global__ void graph_ptr_kernel(const int* __restrict__ gid, int* __restrict__ gp, int n, int G) {
    int v = blockIdx.x * blockDim.x + threadIdx.x;
    if (v > n) return;
    int g0 = (v == 0) ? -1 : gid[v - 1];
    int g1 = (v == n) ? G  : gid[v];
    for (int g = g0 + 1; g <= g1; g++) gp[g] = v;
}

__device__ __forceinline__ float4 bnrelu4(float4 u, float4 A, float4 B) {
    u.x = fmaxf(fmaf(A.x, u.x, B.x), 0.f);
    u.y = fmaxf(fmaf(A.y, u.y, B.y), 0.f);
    u.z = fmaxf(fmaf(A.z, u.z, B.z), 0.f);
    u.w = fmaxf(fmaf(A.w, u.w, B.w), 0.f);
    return u;
}
__device__ __forceinline__ void add4(float4& a, float4 b) {
    a.x += b.x; a.y += b.y; a.z += b.z; a.w += b.w;
}

// ---- fused 32->32 layer: [BN+ReLU input] + CSR mean-gather (float4) + linear + stats ----
// persistent grid, warp per node; lane = (edge_sub<2b>, chan_quad<3b>)
template <bool BN>
__global__ void __launch_bounds__(512, 2)
gcn_layer32(const float* __restrict__ x, const int* __restrict__ rp,
            const int* __restrict__ ci, const float* __restrict__ W,
            const float* __restrict__ bias,
            const double* __restrict__ statsIn,
            const float* __restrict__ gIn, const float* __restrict__ bIn,
            float* __restrict__ out, int n, double* __restrict__ statsOut) {
    __shared__ float  Ws[32 * 32];
    __shared__ float  bs[32];
    __shared__ float  As[32], Bs[32];
    __shared__ __align__(16) float xv[16][32];
    __shared__ double ssum[32], ssq[32];
    int t = threadIdx.x;
    for (int i = t; i < 1024; i += 512) Ws[i] = W[i];
    if (t < 32) {
        bs[t] = bias[t];
        ssum[t] = 0.0; ssq[t] = 0.0;
        if (BN) {
            double m   = statsIn[t] / (double)n;
            double var = statsIn[32 + t] / (double)n - m * m;
            float  rs  = rsqrtf((float)var + EPS);
            float  A   = gIn[t] * rs;
            As[t] = A;
            Bs[t] = bIn[t] - (float)m * A;
        }
    }
    __syncthreads();
    int w = t >> 5, lane = t & 31;
    int eq = lane >> 3, cq = lane & 7;
    float4 A4, B4;
    if (BN) {
        A4 = make_float4(As[cq*4], As[cq*4+1], As[cq*4+2], As[cq*4+3]);
        B4 = make_float4(Bs[cq*4], Bs[cq*4+1], Bs[cq*4+2], Bs[cq*4+3]);
    }
    int warpsTotal = gridDim.x * 16;
    int wg = blockIdx.x * 16 + w;
    double tsum = 0.0, tsq = 0.0;
    for (int v = wg; v < n; v += warpsTotal) {
        int beg = __ldg(&rp[v]), end = __ldg(&rp[v + 1]);
        float4 acc = make_float4(0.f, 0.f, 0.f, 0.f);
        int j = beg;
        for (; j + 8 <= end; j += 8) {
            int s0 = __ldg(&ci[j + eq]);
            int s1 = __ldg(&ci[j + 4 + eq]);
            float4 u0 = __ldg((const float4*)(x + (size_t)s0 * 32) + cq);
            float4 u1 = __ldg((const float4*)(x + (size_t)s1 * 32) + cq);
            if (BN) { u0 = bnrelu4(u0, A4, B4); u1 = bnrelu4(u1, A4, B4); }
            add4(acc, u0);
            add4(acc, u1);
        }
        if (j + 4 <= end) {
            int s0 = __ldg(&ci[j + eq]);
            float4 u0 = __ldg((const float4*)(x + (size_t)s0 * 32) + cq);
            if (BN) u0 = bnrelu4(u0, A4, B4);
            add4(acc, u0);
            j += 4;
        }
        if (j + eq < end) {
            int s0 = __ldg(&ci[j + eq]);
            float4 u0 = __ldg((const float4*)(x + (size_t)s0 * 32) + cq);
            if (BN) u0 = bnrelu4(u0, A4, B4);
            add4(acc, u0);
        }
        // reduce over the 4 edge subgroups (lanes differing in bits 3,4)
#pragma unroll
        for (int off = 8; off <= 16; off <<= 1) {
            acc.x += __shfl_xor_sync(0xffffffffu, acc.x, off);
            acc.y += __shfl_xor_sync(0xffffffffu, acc.y, off);
            acc.z += __shfl_xor_sync(0xffffffffu, acc.z, off);
            acc.w += __shfl_xor_sync(0xffffffffu, acc.w, off);
        }
        float inv = 1.0f / fmaxf((float)(end - beg), 1.0f);
        if (eq == 0) {
            float4 r = make_float4(acc.x * inv, acc.y * inv, acc.z * inv, acc.w * inv);
            *(float4*)&xv[w][cq * 4] = r;
        }
        __syncwarp();
        float o = bs[lane];
#pragma unroll
        for (int i = 0; i < 32; i++) o = fmaf(xv[w][i], Ws[i * 32 + lane], o);
        __syncwarp();
        out[(size_t)v * 32 + lane] = o;
        tsum += (double)o;
        tsq  += (double)o * (double)o;
    }
    atomicAdd(&ssum[lane], tsum);
    atomicAdd(&ssq[lane],  tsq);
    __syncthreads();
    if (t < 32) {
        atomicAdd(&statsOut[t],      ssum[t]);
        atomicAdd(&statsOut[32 + t], ssq[t]);
    }
}

// ---- fold: z[v] = BN(x3[v]) . W3  (warp per node, lane=channel) ----
__global__ void fold_kernel(const float* __restrict__ x3,
                            const double* __restrict__ statsIn,
                            const float* __restrict__ gIn, const float* __restrict__ bIn,
                            const float* __restrict__ W3,
                            float* __restrict__ z, int n) {
    __shared__ float As[32], Bs[32], Wsh[32];
    int t = threadIdx.x;
    if (t < 32) {
        double m   = statsIn[t] / (double)n;
        double var = statsIn[32 + t] / (double)n - m * m;
        float  rs  = rsqrtf((float)var + EPS);
        float  A   = gIn[t] * rs;
        As[t] = A;
        Bs[t] = bIn[t] - (float)m * A;
        Wsh[t] = W3[t];
    }
    __syncthreads();
    int w = t >> 5, lane = t & 31;
    int v = blockIdx.x * 8 + w;
    if (v >= n) return;
    float val = x3[(size_t)v * 32 + lane];
    val = fmaxf(fmaf(As[lane], val, Bs[lane]), 0.f) * Wsh[lane];
#pragma unroll
    for (int off = 16; off; off >>= 1) val += __shfl_down_sync(0xffffffffu, val, off);
    if (lane == 0) z[v] = val;
}

// ---- layer 4: scalar mean-gather of z + bias + stats ----
__global__ void __launch_bounds__(512, 2)
layer4_kernel(const float* __restrict__ z, const int* __restrict__ rp,
              const int* __restrict__ ci, const float* __restrict__ b3,
              float* __restrict__ out, int n, double* __restrict__ statsOut) {
    __shared__ double ssum, ssq;
    int t = threadIdx.x;
    if (t == 0) { ssum = 0.0; ssq = 0.0; }
    __syncthreads();
    int w = t >> 5, lane = t & 31;
    int warpsTotal = gridDim.x * 16;
    int wg = blockIdx.x * 16 + w;
    float bias = b3[0];
    double tsum = 0.0, tsq = 0.0;
    for (int v = wg; v < n; v += warpsTotal) {
        int beg = __ldg(&rp[v]), end = __ldg(&rp[v + 1]);
        float s = 0.f;
        for (int j = beg + lane; j < end; j += 32) s += z[__ldg(&ci[j])];
#pragma unroll
        for (int off = 16; off; off >>= 1) s += __shfl_down_sync(0xffffffffu, s, off);
        if (lane == 0) {
            float o = s / fmaxf((float)(end - beg), 1.0f) + bias;
            out[v] = o;
            tsum += (double)o;
            tsq  += (double)o * (double)o;
        }
    }
    if (lane == 0) {
        atomicAdd(&ssum, tsum);
        atomicAdd(&ssq,  tsq);
    }
    __syncthreads();
    if (t == 0) {
        atomicAdd(&statsOut[0],  ssum);
        atomicAdd(&statsOut[32], ssq);
    }
}

// ---- fused per-graph mean pool (BN applied on the fly) + MLP head ----
__global__ void pool_mlp_kernel(const float* __restrict__ h,  const float* __restrict__ x1,
                                const float* __restrict__ x2, const float* __restrict__ x3,
                                const float* __restrict__ x4, const int* __restrict__ gp,
                                const double* __restrict__ stats,
                                const float* __restrict__ g0, const float* __restrict__ be0,
                                const float* __restrict__ g1, const float* __restrict__ be1,
                                const float* __restrict__ g2, const float* __restrict__ be2,
                                const float* __restrict__ g3, const float* __restrict__ be3,
                                const float* __restrict__ W0, const float* __restrict__ b0,
                                const float* __restrict__ W1, const float* __restrict__ b1,
                                const float* __restrict__ W2, const float* __restrict__ b2,
                                float* __restrict__ out, int n) {
    __shared__ float As[97], Bs[97];
    __shared__ float hr[129];
    __shared__ float l0[128];
    __shared__ float l1[64];
    int t = threadIdx.x;
    if (t < 97) {
        int layer = (t < 96) ? (t >> 5) : 3;
        int c     = (t < 96) ? (t & 31) : 0;
        const double* st = stats + layer * 64;
        const float* gg = (layer == 0) ? g0 : (layer == 1) ? g1 : (layer == 2) ? g2 : g3;
        const float* bb = (layer == 0) ? be0 : (layer == 1) ? be1 : (layer == 2) ? be2 : be3;
        double m   = st[c] / (double)n;
        double var = st[32 + c] / (double)n - m * m;
        float  rs  = rsqrtf((float)var + EPS);
        float  A   = gg[c] * rs;
        As[t] = A;
        Bs[t] = bb[c] - (float)m * A;
    }
    __syncthreads();
    int g = blockIdx.x;
    int beg = gp[g], end = gp[g + 1];
    float inv = 1.0f / fmaxf((float)(end - beg), 1.0f);
    int w = t >> 5, c = t & 31;
    {
        const float* p = (w == 0) ? h : (w == 1) ? x1 : (w == 2) ? x2 : x3;
        float s = 0.f;
        if (w == 0) {
            int v = beg;
            for (; v + 4 <= end; v += 4) {
                float a = p[v * 32 + c],       b = p[(v + 1) * 32 + c];
                float d = p[(v + 2) * 32 + c], e = p[(v + 3) * 32 + c];
                s += (a + b) + (d + e);
            }
            for (; v < end; v++) s += p[v * 32 + c];
        } else {
            float A = As[(w - 1) * 32 + c];
            float B = Bs[(w - 1) * 32 + c];
            int v = beg;
            for (; v + 4 <= end; v += 4) {
                float a = p[v * 32 + c],       b = p[(v + 1) * 32 + c];
                float d = p[(v + 2) * 32 + c], e = p[(v + 3) * 32 + c];
                a = fmaxf(fmaf(A, a, B), 0.f); b = fmaxf(fmaf(A, b, B), 0.f);
                d = fmaxf(fmaf(A, d, B), 0.f); e = fmaxf(fmaf(A, e, B), 0.f);
                s += (a + b) + (d + e);
            }
            for (; v < end; v++) s += fmaxf(fmaf(A, p[v * 32 + c], B), 0.f);
        }
        hr[t] = s * inv;
    }
    if (t == 0) {
        float A = As[96], B = Bs[96];
        float s = 0.f;
        int v = beg;
        for (; v + 4 <= end; v += 4) {
            float a = fmaxf(fmaf(A, x4[v], B), 0.f);
            float b = fmaxf(fmaf(A, x4[v + 1], B), 0.f);
            float d = fmaxf(fmaf(A, x4[v + 2], B), 0.f);
            float e = fmaxf(fmaf(A, x4[v + 3], B), 0.f);
            s += (a + b) + (d + e);
        }
        for (; v < end; v++) s += fmaxf(fmaf(A, x4[v], B), 0.f);
        hr[128] = s * inv;
    }
    __syncthreads();
    {
        float acc = b0[t];
#pragma unroll 4
        for (int i = 0; i < 129; i++) acc = fmaf(hr[i], W0[i * 128 + t], acc);
        l0[t] = fmaxf(acc, 0.0f);
    }
    __syncthreads();
    if (t < 64) {
        float acc = b1[t];
#pragma unroll 4
        for (int i = 0; i < 128; i++) acc = fmaf(l0[i], W1[i * 64 + t], acc);
        l1[t] = fmaxf(acc, 0.0f);
    }
    __syncthreads();
    if (t == 0) {
        float acc = b2[0];
        for (int i = 0; i < 64; i++) acc = fmaf(l1[i], W2[i], acc);
        out[g] = acc;
    }
}

extern "C" void kernel_launch(void* const* d_in, const int* in_sizes, int n_in,
                              void* d_out, int out_size) {
    const float* h   = (const float*)d_in[0];
    const int*   src = (const int*)d_in[1];
    const int*   dst = (const int*)d_in[2];
    const int*   gid = (const int*)d_in[3];
    const int E = in_sizes[1];
    const int N = in_sizes[3];
    const int G = out_size;
    float* out = (float*)d_out;

    const float* cw[4]; const float* cb[4]; const float* bg[4]; const float* bb[4];
    for (int i = 0; i < 4; i++) {
        cw[i] = (const float*)d_in[4 + 4 * i + 0];
        cb[i] = (const float*)d_in[4 + 4 * i + 1];
        bg[i] = (const float*)d_in[4 + 4 * i + 2];
        bb[i] = (const float*)d_in[4 + 4 * i + 3];
    }
    const float* W0 = (const float*)d_in[20];
    const float* b0 = (const float*)d_in[21];
    const float* W1 = (const float*)d_in[22];
    const float* b1 = (const float*)d_in[23];
    const float* W2 = (const float*)d_in[24];
    const float* b2 = (const float*)d_in[25];

    int *hist, *rp, *pos, *ci, *gp;
    float *x1, *x2, *x3, *x4, *z;
    double *stats;
    cudaGetSymbolAddress((void**)&hist,  g_hist);
    cudaGetSymbolAddress((void**)&rp,    g_rp);
    cudaGetSymbolAddress((void**)&pos,   g_pos);
    cudaGetSymbolAddress((void**)&ci,    g_ci);
    cudaGetSymbolAddress((void**)&gp,    g_gp);
    cudaGetSymbolAddress((void**)&x1,    g_x1);
    cudaGetSymbolAddress((void**)&x2,    g_x2);
    cudaGetSymbolAddress((void**)&x3,    g_x3);
    cudaGetSymbolAddress((void**)&x4,    g_x4);
    cudaGetSymbolAddress((void**)&z,     g_z);
    cudaGetSymbolAddress((void**)&stats, g_stats);

    const int T = 256;

    // ---- CSR build + init ----
    cudaMemsetAsync(hist,  0, (size_t)N * sizeof(int));
    cudaMemsetAsync(stats, 0, 4 * 64 * sizeof(double));
    hist_kernel<<<(E + T - 1) / T, T>>>(dst, hist, E);
    scan_kernel<<<1, 1024>>>(hist, rp, N);
    cudaMemcpyAsync(pos, rp, (size_t)N * sizeof(int), cudaMemcpyDeviceToDevice);
    fill_kernel<<<(E + T - 1) / T, T>>>(src, dst, pos, ci, E);
    graph_ptr_kernel<<<(N + 1 + T - 1) / T, T>>>(gid, gp, N, G);

    // ---- GCN layers ----
    const int LG = 296, LT = 512;
    gcn_layer32<false><<<LG, LT>>>(h,  rp, ci, cw[0], cb[0],
                                   nullptr, nullptr, nullptr,
                                   x1, N, stats + 0 * 64);
    gcn_layer32<true><<<LG, LT>>>(x1, rp, ci, cw[1], cb[1],
                                  stats + 0 * 64, bg[0], bb[0],
                                  x2, N, stats + 1 * 64);
    gcn_layer32<true><<<LG, LT>>>(x2, rp, ci, cw[2], cb[2],
                                  stats + 1 * 64, bg[1], bb[1],
                                  x3, N, stats + 2 * 64);
    // layer 4: fold BN(x3)·W3 into scalars, then scalar gather
    fold_kernel<<<(N + 7) / 8, 256>>>(x3, stats + 2 * 64, bg[2], bb[2], cw[3], z, N);
    layer4_kernel<<<LG, LT>>>(z, rp, ci, cb[3], x4, N, stats + 3 * 64);

    // ---- fused pool + MLP ----
    pool_mlp_kernel<<<G, 128>>>(h, x1, x2, x3, x4, gp, stats,
                                bg[0], bb[0], bg[1], bb[1], bg[2], bb[2], bg[3], bb[3],
                                W0, b0, W1, b1, W2, b2, out, N);
}

// round 6
// speedup vs baseline: 4.2404x; 1.2128x over previous
#include <cuda_runtime.h>
#include <cuda_bf16.h>
#include <cuda_fp16.h>

#define NMAX 100000
#define EMAX 1600000
#define GMAX 1000
#define EPS 1e-5f

// ---- scratch (static device globals; no allocation) ----
__device__ int    g_hist[NMAX];
__device__ int    g_rp  [NMAX + 1];   // CSR row ptr (by dst)
__device__ int    g_pos [NMAX];       // fill cursor
__device__ int    g_ci  [EMAX];       // CSR col idx (src)
__device__ int    g_gp  [GMAX + 1];   // per-graph node ranges
__device__ int    g_tsum[16384];      // scan partials
__device__ __align__(16) __half g_h16[NMAX * 32];
__device__ __align__(16) __half g_x1 [NMAX * 32];  // raw linear outputs (pre-BN), fp16
__device__ __align__(16) __half g_x2 [NMAX * 32];
__device__ __align__(16) __half g_x3 [NMAX * 32];
__device__ float  g_x4  [NMAX];
__device__ float  g_z   [NMAX];       // folded BN(x3)·W3
__device__ double g_stats[4 * 64];    // per layer: [0..31]=sum, [32..63]=sumsq

// ---- convert h (fp32) -> fp16 ----
__global__ void h2half_kernel(const float* __restrict__ h, __half* __restrict__ h16, int n32) {
    int j = blockIdx.x * blockDim.x + threadIdx.x;   // handles 8 floats
    if (j * 8 >= n32) return;
    const float4* hf = (const float4*)h;
    float4 a = hf[2 * j], b = hf[2 * j + 1];
    __half2 p0 = __floats2half2_rn(a.x, a.y);
    __half2 p1 = __floats2half2_rn(a.z, a.w);
    __half2 p2 = __floats2half2_rn(b.x, b.y);
    __half2 p3 = __floats2half2_rn(b.z, b.w);
    uint4 u;
    u.x = *(unsigned*)&p0; u.y = *(unsigned*)&p1;
    u.z = *(unsigned*)&p2; u.w = *(unsigned*)&p3;
    ((uint4*)h16)[j] = u;
}

// ---- histogram of dst ----
__global__ void hist_kernel(const int* __restrict__ dst, int* __restrict__ hist, int E) {
    int e = blockIdx.x * blockDim.x + threadIdx.x;
    if (e < E) atomicAdd(&hist[dst[e]], 1);
}

// ---- 3-phase exclusive scan over n entries -> rp[0..n] ----
#define SCAN_THREADS 16384
__global__ void scan_p1(const int* __restrict__ in, int* __restrict__ tsum, int n, int chunk) {
    int t = blockIdx.x * blockDim.x + threadIdx.x;
    int begin = t * chunk, end = min(begin + chunk, n);
    int s = 0;
    for (int i = begin; i < end; i++) s += in[i];
    tsum[t] = s;
}
__global__ void scan_p2(int* __restrict__ tsum) {
    __shared__ int ps[1024];
    int t = threadIdx.x;
    int s = 0;
#pragma unroll
    for (int k = 0; k < 16; k++) s += tsum[t * 16 + k];
    ps[t] = s;
    __syncthreads();
    for (int off = 1; off < 1024; off <<= 1) {
        int v = (t >= off) ? ps[t - off] : 0;
        __syncthreads();
        ps[t] += v;
        __syncthreads();
    }
    int run = ps[t] - s;   // exclusive
#pragma unroll
    for (int k = 0; k < 16; k++) { int v = tsum[t * 16 + k]; tsum[t * 16 + k] = run; run += v; }
}
__global__ void scan_p3(const int* __restrict__ in, const int* __restrict__ tsum,
                        int* __restrict__ out, int n, int chunk) {
    int t = blockIdx.x * blockDim.x + threadIdx.x;
    int begin = t * chunk, end = min(begin + chunk, n);
    int off = tsum[t];
    for (int i = begin; i < end; i++) { int v = in[i]; out[i] = off; off += v; }
    if (end == n && begin < n) out[n] = off;
}

// ---- fill CSR: slot per edge via atomic cursor ----
__global__ void fill_kernel(const int* __restrict__ src, const int* __restrict__ dst,
                            int* __restrict__ pos, int* __restrict__ ci, int E) {
    int e = blockIdx.x * blockDim.x + threadIdx.x;
    if (e < E) {
        int slot = atomicAdd(&pos[dst[e]], 1);
        ci[slot] = src[e];
    }
}

// ---- graph ranges via boundary scatter (gid sorted) ----
__global__ void graph_ptr_kernel(const int* __restrict__ gid, int* __restrict__ gp, int n, int G) {
    int v = blockIdx.x * blockDim.x + threadIdx.x;
    if (v > n) return;
    int g0 = (v == 0) ? -1 : gid[v - 1];
    int g1 = (v == n) ? G  : gid[v];
    for (int g = g0 + 1; g <= g1; g++) gp[g] = v;
}

// ---- fused 32->32 layer, fp16 in/out ----
// warp per node; lane = (edge_sub eq = lane>>2, chan_oct cq = lane&3)
// each lane loads 16B = 8 fp16 channels; one warp LDG covers 8 edges.
template <bool BN>
__global__ void __launch_bounds__(512, 2)
gcn_layer32h(const __half* __restrict__ x, const int* __restrict__ rp,
             const int* __restrict__ ci, const float* __restrict__ W,
             const float* __restrict__ bias,
             const double* __restrict__ statsIn,
             const float* __restrict__ gIn, const float* __restrict__ bIn,
             __half* __restrict__ out, int n, double* __restrict__ statsOut) {
    __shared__ float  Ws[32 * 32];
    __shared__ float  bs[32];
    __shared__ float  As[32], Bs[32];
    __shared__ __align__(16) float xv[16][32];
    __shared__ double ssum[32], ssq[32];
    int t = threadIdx.x;
    for (int i = t; i < 1024; i += 512) Ws[i] = W[i];
    if (t < 32) {
        bs[t] = bias[t];
        ssum[t] = 0.0; ssq[t] = 0.0;
        if (BN) {
            double m   = statsIn[t] / (double)n;
            double var = statsIn[32 + t] / (double)n - m * m;
            float  rs  = rsqrtf((float)var + EPS);
            float  A   = gIn[t] * rs;
            As[t] = A;
            Bs[t] = bIn[t] - (float)m * A;
        }
    }
    __syncthreads();
    int w = t >> 5, lane = t & 31;
    int eq = lane >> 2, cq = lane & 3;
    float A8[8], B8[8];
    if (BN) {
#pragma unroll
        for (int k = 0; k < 8; k++) { A8[k] = As[cq * 8 + k]; B8[k] = Bs[cq * 8 + k]; }
    }
    int warpsTotal = gridDim.x * 16;
    int wg = blockIdx.x * 16 + w;
    float tsum = 0.f, tsq = 0.f;
    double dsum = 0.0, dsq = 0.0;
    for (int v = wg; v < n; v += warpsTotal) {
        int beg = __ldg(&rp[v]), end = __ldg(&rp[v + 1]);
        float acc[8];
#pragma unroll
        for (int k = 0; k < 8; k++) acc[k] = 0.f;

        auto accum = [&](uint4 u) {
            __half2 h0 = *(__half2*)&u.x, h1 = *(__half2*)&u.y;
            __half2 h2 = *(__half2*)&u.z, h3 = *(__half2*)&u.w;
            float2 f0 = __half22float2(h0), f1 = __half22float2(h1);
            float2 f2 = __half22float2(h2), f3 = __half22float2(h3);
            float f[8] = {f0.x, f0.y, f1.x, f1.y, f2.x, f2.y, f3.x, f3.y};
#pragma unroll
            for (int k = 0; k < 8; k++) {
                float vv = f[k];
                if (BN) vv = fmaxf(fmaf(A8[k], vv, B8[k]), 0.f);
                acc[k] += vv;
            }
        };

        int j = beg;
        for (; j + 16 <= end; j += 16) {
            int s0 = __ldg(&ci[j + eq]);
            int s1 = __ldg(&ci[j + 8 + eq]);
            uint4 u0 = __ldg((const uint4*)(x + (size_t)s0 * 32) + cq);
            uint4 u1 = __ldg((const uint4*)(x + (size_t)s1 * 32) + cq);
            accum(u0);
            accum(u1);
        }
        if (j + 8 <= end) {
            int s0 = __ldg(&ci[j + eq]);
            uint4 u0 = __ldg((const uint4*)(x + (size_t)s0 * 32) + cq);
            accum(u0);
            j += 8;
        }
        if (j + eq < end) {
            int s0 = __ldg(&ci[j + eq]);
            uint4 u0 = __ldg((const uint4*)(x + (size_t)s0 * 32) + cq);
            accum(u0);
        }
        // reduce over 8 edge subgroups (lane bits 2,3,4)
#pragma unroll
        for (int k = 0; k < 8; k++) {
            acc[k] += __shfl_xor_sync(0xffffffffu, acc[k], 4);
            acc[k] += __shfl_xor_sync(0xffffffffu, acc[k], 8);
            acc[k] += __shfl_xor_sync(0xffffffffu, acc[k], 16);
        }
        float inv = 1.0f / fmaxf((float)(end - beg), 1.0f);
        if (eq == 0) {
            *(float4*)&xv[w][cq * 8]     = make_float4(acc[0]*inv, acc[1]*inv, acc[2]*inv, acc[3]*inv);
            *(float4*)&xv[w][cq * 8 + 4] = make_float4(acc[4]*inv, acc[5]*inv, acc[6]*inv, acc[7]*inv);
        }
        __syncwarp();
        float o = bs[lane];
#pragma unroll
        for (int i = 0; i < 32; i++) o = fmaf(xv[w][i], Ws[i * 32 + lane], o);
        __syncwarp();
        tsum += o;
        tsq  += o * o;
        float onb = __shfl_xor_sync(0xffffffffu, o, 1);
        if ((lane & 1) == 0) {
            __half2 hv = __floats2half2_rn(o, onb);
            ((__half2*)out)[(size_t)v * 16 + (lane >> 1)] = hv;
        }
        // fold float partials into double every iteration chunk to keep error tiny
        dsum += (double)tsum; dsq += (double)tsq;
        tsum = 0.f; tsq = 0.f;
    }
    atomicAdd(&ssum[lane], dsum);
    atomicAdd(&ssq[lane],  dsq);
    __syncthreads();
    if (t < 32) {
        atomicAdd(&statsOut[t],      ssum[t]);
        atomicAdd(&statsOut[32 + t], ssq[t]);
    }
}

// ---- fold: z[v] = BN(x3[v]) . W3  (warp per node, lane=channel) ----
__global__ void fold_kernel(const __half* __restrict__ x3,
                            const double* __restrict__ statsIn,
                            const float* __restrict__ gIn, const float* __restrict__ bIn,
                            const float* __restrict__ W3,
                            float* __restrict__ z, int n) {
    __shared__ float As[32], Bs[32], Wsh[32];
    int t = threadIdx.x;
    if (t < 32) {
        double m   = statsIn[t] / (double)n;
        double var = statsIn[32 + t] / (double)n - m * m;
        float  rs  = rsqrtf((float)var + EPS);
        float  A   = gIn[t] * rs;
        As[t] = A;
        Bs[t] = bIn[t] - (float)m * A;
        Wsh[t] = W3[t];
    }
    __syncthreads();
    int w = t >> 5, lane = t & 31;
    int v = blockIdx.x * 8 + w;
    if (v >= n) return;
    float val = __half2float(x3[(size_t)v * 32 + lane]);
    val = fmaxf(fmaf(As[lane], val, Bs[lane]), 0.f) * Wsh[lane];
#pragma unroll
    for (int off = 16; off; off >>= 1) val += __shfl_down_sync(0xffffffffu, val, off);
    if (lane == 0) z[v] = val;
}

// ---- layer 4: scalar mean-gather of z + bias + stats ----
__global__ void __launch_bounds__(512, 2)
layer4_kernel(const float* __restrict__ z, const int* __restrict__ rp,
              const int* __restrict__ ci, const float* __restrict__ b3,
              float* __restrict__ out, int n, double* __restrict__ statsOut) {
    __shared__ double ssum, ssq;
    int t = threadIdx.x;
    if (t == 0) { ssum = 0.0; ssq = 0.0; }
    __syncthreads();
    int w = t >> 5, lane = t & 31;
    int warpsTotal = gridDim.x * 16;
    int wg = blockIdx.x * 16 + w;
    float bias = b3[0];
    double tsum = 0.0, tsq = 0.0;
    for (int v = wg; v < n; v += warpsTotal) {
        int beg = __ldg(&rp[v]), end = __ldg(&rp[v + 1]);
        float s = 0.f;
        for (int j = beg + lane; j < end; j += 32) s += z[__ldg(&ci[j])];
#pragma unroll
        for (int off = 16; off; off >>= 1) s += __shfl_down_sync(0xffffffffu, s, off);
        if (lane == 0) {
            float o = s / fmaxf((float)(end - beg), 1.0f) + bias;
            out[v] = o;
            tsum += (double)o;
            tsq  += (double)o * (double)o;
        }
    }
    if (lane == 0) {
        atomicAdd(&ssum, tsum);
        atomicAdd(&ssq,  tsq);
    }
    __syncthreads();
    if (t == 0) {
        atomicAdd(&statsOut[0],  ssum);
        atomicAdd(&statsOut[32], ssq);
    }
}

// ---- fused per-graph mean pool (BN on the fly; x1..x3 fp16) + MLP head ----
__global__ void pool_mlp_kernel(const float* __restrict__ h,  const __half* __restrict__ x1,
                                const __half* __restrict__ x2, const __half* __restrict__ x3,
                                const float* __restrict__ x4, const int* __restrict__ gp,
                                const double* __restrict__ stats,
                                const float* __restrict__ g0, const float* __restrict__ be0,
                                const float* __restrict__ g1, const float* __restrict__ be1,
                                const float* __restrict__ g2, const float* __restrict__ be2,
                                const float* __restrict__ g3, const float* __restrict__ be3,
                                const float* __restrict__ W0, const float* __restrict__ b0,
                                const float* __restrict__ W1, const float* __restrict__ b1,
                                const float* __restrict__ W2, const float* __restrict__ b2,
                                float* __restrict__ out, int n) {
    __shared__ float As[97], Bs[97];
    __shared__ float hr[129];
    __shared__ float l0[128];
    __shared__ float l1[64];
    int t = threadIdx.x;
    if (t < 97) {
        int layer = (t < 96) ? (t >> 5) : 3;
        int c     = (t < 96) ? (t & 31) : 0;
        const double* st = stats + layer * 64;
        const float* gg = (layer == 0) ? g0 : (layer == 1) ? g1 : (layer == 2) ? g2 : g3;
        const float* bb = (layer == 0) ? be0 : (layer == 1) ? be1 : (layer == 2) ? be2 : be3;
        double m   = st[c] / (double)n;
        double var = st[32 + c] / (double)n - m * m;
        float  rs  = rsqrtf((float)var + EPS);
        float  A   = gg[c] * rs;
        As[t] = A;
        Bs[t] = bb[c] - (float)m * A;
    }
    __syncthreads();
    int g = blockIdx.x;
    int beg = gp[g], end = gp[g + 1];
    float inv = 1.0f / fmaxf((float)(end - beg), 1.0f);
    int w = t >> 5, c = t & 31;
    {
        float s = 0.f;
        if (w == 0) {
            int v = beg;
            for (; v + 4 <= end; v += 4) {
                float a = h[v * 32 + c],       b = h[(v + 1) * 32 + c];
                float d = h[(v + 2) * 32 + c], e = h[(v + 3) * 32 + c];
                s += (a + b) + (d + e);
            }
            for (; v < end; v++) s += h[v * 32 + c];
        } else {
            const __half* p = (w == 1) ? x1 : (w == 2) ? x2 : x3;
            float A = As[(w - 1) * 32 + c + 32 - 32];
            // note: layer index for warp w is w-1... but As index base is (w-1)*32
            A = As[(w - 1) * 32 + c];
            float B = Bs[(w - 1) * 32 + c];
            int v = beg;
            for (; v + 4 <= end; v += 4) {
                float a = __half2float(p[(size_t)v * 32 + c]);
                float b = __half2float(p[(size_t)(v + 1) * 32 + c]);
                float d = __half2float(p[(size_t)(v + 2) * 32 + c]);
                float e = __half2float(p[(size_t)(v + 3) * 32 + c]);
                a = fmaxf(fmaf(A, a, B), 0.f); b = fmaxf(fmaf(A, b, B), 0.f);
                d = fmaxf(fmaf(A, d, B), 0.f); e = fmaxf(fmaf(A, e, B), 0.f);
                s += (a + b) + (d + e);
            }
            for (; v < end; v++) s += fmaxf(fmaf(A, __half2float(p[(size_t)v * 32 + c]), B), 0.f);
        }
        hr[t] = s * inv;
    }
    if (t == 0) {
        float A = As[96], B = Bs[96];
        float s = 0.f;
        int v = beg;
        for (; v + 4 <= end; v += 4) {
            float a = fmaxf(fmaf(A, x4[v], B), 0.f);
            float b = fmaxf(fmaf(A, x4[v + 1], B), 0.f);
            float d = fmaxf(fmaf(A, x4[v + 2], B), 0.f);
            float e = fmaxf(fmaf(A, x4[v + 3], B), 0.f);
            s += (a + b) + (d + e);
        }
        for (; v < end; v++) s += fmaxf(fmaf(A, x4[v], B), 0.f);
        hr[128] = s * inv;
    }
    __syncthreads();
    {
        float acc = b0[t];
#pragma unroll 4
        for (int i = 0; i < 129; i++) acc = fmaf(hr[i], W0[i * 128 + t], acc);
        l0[t] = fmaxf(acc, 0.0f);
    }
    __syncthreads();
    if (t < 64) {
        float acc = b1[t];
#pragma unroll 4
        for (int i = 0; i < 128; i++) acc = fmaf(l0[i], W1[i * 64 + t], acc);
        l1[t] = fmaxf(acc, 0.0f);
    }
    __syncthreads();
    if (t == 0) {
        float acc = b2[0];
        for (int i = 0; i < 64; i++) acc = fmaf(l1[i], W2[i], acc);
        out[g] = acc;
    }
}

extern "C" void kernel_launch(void* const* d_in, const int* in_sizes, int n_in,
                              void* d_out, int out_size) {
    const float* h   = (const float*)d_in[0];
    const int*   src = (const int*)d_in[1];
    const int*   dst = (const int*)d_in[2];
    const int*   gid = (const int*)d_in[3];
    const int E = in_sizes[1];
    const int N = in_sizes[3];
    const int G = out_size;
    float* out = (float*)d_out;

    const float* cw[4]; const float* cb[4]; const float* bg[4]; const float* bb[4];
    for (int i = 0; i < 4; i++) {
        cw[i] = (const float*)d_in[4 + 4 * i + 0];
        cb[i] = (const float*)d_in[4 + 4 * i + 1];
        bg[i] = (const float*)d_in[4 + 4 * i + 2];
        bb[i] = (const float*)d_in[4 + 4 * i + 3];
    }
    const float* W0 = (const float*)d_in[20];
    const float* b0 = (const float*)d_in[21];
    const float* W1 = (const float*)d_in[22];
    const float* b1 = (const float*)d_in[23];
    const float* W2 = (const float*)d_in[24];
    const float* b2 = (const float*)d_in[25];

    int *hist, *rp, *pos, *ci, *gp, *tsum;
    __half *h16, *x1, *x2, *x3;
    float *x4, *z;
    double *stats;
    cudaGetSymbolAddress((void**)&hist,  g_hist);
    cudaGetSymbolAddress((void**)&rp,    g_rp);
    cudaGetSymbolAddress((void**)&pos,   g_pos);
    cudaGetSymbolAddress((void**)&ci,    g_ci);
    cudaGetSymbolAddress((void**)&gp,    g_gp);
    cudaGetSymbolAddress((void**)&tsum,  g_tsum);
    cudaGetSymbolAddress((void**)&h16,   g_h16);
    cudaGetSymbolAddress((void**)&x1,    g_x1);
    cudaGetSymbolAddress((void**)&x2,    g_x2);
    cudaGetSymbolAddress((void**)&x3,    g_x3);
    cudaGetSymbolAddress((void**)&x4,    g_x4);
    cudaGetSymbolAddress((void**)&z,     g_z);
    cudaGetSymbolAddress((void**)&stats, g_stats);

    const int T = 256;

    // ---- CSR build + init ----
    cudaMemsetAsync(hist,  0, (size_t)N * sizeof(int));
    cudaMemsetAsync(stats, 0, 4 * 64 * sizeof(double));
    h2half_kernel<<<(N * 32 / 8 + T - 1) / T, T>>>(h, h16, N * 32);
    hist_kernel<<<(E + T - 1) / T, T>>>(dst, hist, E);
    {
        int chunk = (N + SCAN_THREADS - 1) / SCAN_THREADS;
        scan_p1<<<SCAN_THREADS / 256, 256>>>(hist, tsum, N, chunk);
        scan_p2<<<1, 1024>>>(tsum);
        scan_p3<<<SCAN_THREADS / 256, 256>>>(hist, tsum, rp, N, chunk);
    }
    cudaMemcpyAsync(pos, rp, (size_t)N * sizeof(int), cudaMemcpyDeviceToDevice);
    fill_kernel<<<(E + T - 1) / T, T>>>(src, dst, pos, ci, E);
    graph_ptr_kernel<<<(N + 1 + T - 1) / T, T>>>(gid, gp, N, G);

    // ---- GCN layers ----
    const int LG = 296, LT = 512;
    gcn_layer32h<false><<<LG, LT>>>(h16, rp, ci, cw[0], cb[0],
                                    nullptr, nullptr, nullptr,
                                    x1, N, stats + 0 * 64);
    gcn_layer32h<true><<<LG, LT>>>(x1, rp, ci, cw[1], cb[1],
                                   stats + 0 * 64, bg[0], bb[0],
                                   x2, N, stats + 1 * 64);
    gcn_layer32h<true><<<LG, LT>>>(x2, rp, ci, cw[2], cb[2],
                                   stats + 1 * 64, bg[1], bb[1],
                                   x3, N, stats + 2 * 64);
    fold_kernel<<<(N + 7) / 8, 256>>>(x3, stats + 2 * 64, bg[2], bb[2], cw[3], z, N);
    layer4_kernel<<<LG, LT>>>(z, rp, ci, cb[3], x4, N, stats + 3 * 64);

    // ---- fused pool + MLP ----
    pool_mlp_kernel<<<G, 128>>>(h, x1, x2, x3, x4, gp, stats,
                                bg[0], bb[0], bg[1], bb[1], bg[2], bb[2], bg[3], bb[3],
                                W0, b0, W1, b1, W2, b2, out, N);
}

// round 7
// speedup vs baseline: 4.4540x; 1.0504x over previous
#include <cuda_runtime.h>
#include <cuda_bf16.h>
#include <cuda_fp16.h>

#define NMAX 100000
#define EMAX 1600000
#define GMAX 1000
#define EPS 1e-5f

// ---- scratch (static device globals; no allocation) ----
__device__ int    g_hist[NMAX];
__device__ int    g_rp  [NMAX + 1];   // CSR row ptr (by dst)
__device__ int    g_pos [NMAX];       // fill cursor
__device__ int    g_ci  [EMAX];       // CSR col idx (src)
__device__ int    g_gp  [GMAX + 1];   // per-graph node ranges
__device__ __align__(16) int g_tsum[4096];  // scan partials
__device__ __align__(16) __half g_h16[NMAX * 32];
__device__ __align__(16) __half g_x1 [NMAX * 32];  // raw linear outputs (pre-BN), fp16
__device__ __align__(16) __half g_x2 [NMAX * 32];
__device__ __align__(16) __half g_x3 [NMAX * 32];
__device__ float  g_x4  [NMAX];
__device__ float  g_z   [NMAX];       // folded BN(x3)·W3
__device__ double g_stats[4 * 64];    // per layer: [0..31]=sum, [32..63]=sumsq

// ---- convert h (fp32) -> fp16 ----
__global__ void h2half_kernel(const float* __restrict__ h, __half* __restrict__ h16, int n32) {
    int j = blockIdx.x * blockDim.x + threadIdx.x;   // handles 8 floats
    if (j * 8 >= n32) return;
    const float4* hf = (const float4*)h;
    float4 a = hf[2 * j], b = hf[2 * j + 1];
    __half2 p0 = __floats2half2_rn(a.x, a.y);
    __half2 p1 = __floats2half2_rn(a.z, a.w);
    __half2 p2 = __floats2half2_rn(b.x, b.y);
    __half2 p3 = __floats2half2_rn(b.z, b.w);
    uint4 u;
    u.x = *(unsigned*)&p0; u.y = *(unsigned*)&p1;
    u.z = *(unsigned*)&p2; u.w = *(unsigned*)&p3;
    ((uint4*)h16)[j] = u;
}

// ---- histogram of dst ----
__global__ void hist_kernel(const int* __restrict__ dst, int* __restrict__ hist, int E) {
    int e = blockIdx.x * blockDim.x + threadIdx.x;
    if (e < E) atomicAdd(&hist[dst[e]], 1);
}

// ---- 3-phase exclusive scan over n entries -> rp[0..n] ----
#define SCAN_THREADS 4096
__global__ void scan_p1(const int* __restrict__ in, int* __restrict__ tsum, int n, int chunk) {
    int t = blockIdx.x * blockDim.x + threadIdx.x;
    int begin = t * chunk, end = min(begin + chunk, n);
    int s = 0;
    for (int i = begin; i < end; i++) s += in[i];
    tsum[t] = s;
}
// 4096 partials scanned by 1024 threads via warp shuffles
__global__ void scan_p2(int* __restrict__ tsum) {
    __shared__ int wsum[32];
    int t = threadIdx.x;
    int lane = t & 31, wid = t >> 5;
    int4 v = ((const int4*)tsum)[t];
    int s = ((v.x + v.y) + (v.z + v.w));
    int sc = s;
#pragma unroll
    for (int off = 1; off < 32; off <<= 1) {
        int u = __shfl_up_sync(0xffffffffu, sc, off);
        if (lane >= off) sc += u;
    }
    if (lane == 31) wsum[wid] = sc;
    __syncthreads();
    if (wid == 0) {
        int ws = wsum[lane];
        int wsc = ws;
#pragma unroll
        for (int off = 1; off < 32; off <<= 1) {
            int u = __shfl_up_sync(0xffffffffu, wsc, off);
            if (lane >= off) wsc += u;
        }
        wsum[lane] = wsc - ws;   // exclusive warp base
    }
    __syncthreads();
    int base = wsum[wid] + (sc - s);  // exclusive prefix for this thread's 4 entries
    int4 o;
    o.x = base;         base += v.x;
    o.y = base;         base += v.y;
    o.z = base;         base += v.z;
    o.w = base;
    ((int4*)tsum)[t] = o;
}
__global__ void scan_p3(const int* __restrict__ in, const int* __restrict__ tsum,
                        int* __restrict__ out, int n, int chunk) {
    int t = blockIdx.x * blockDim.x + threadIdx.x;
    int begin = t * chunk, end = min(begin + chunk, n);
    int off = tsum[t];
    for (int i = begin; i < end; i++) { int v = in[i]; out[i] = off; off += v; }
    if (end == n && begin < n) out[n] = off;
}

// ---- fill CSR: slot per edge via atomic cursor ----
__global__ void fill_kernel(const int* __restrict__ src, const int* __restrict__ dst,
                            int* __restrict__ pos, int* __restrict__ ci, int E) {
    int e = blockIdx.x * blockDim.x + threadIdx.x;
    if (e < E) {
        int slot = atomicAdd(&pos[dst[e]], 1);
        ci[slot] = src[e];
    }
}

// ---- graph ranges via boundary scatter (gid sorted) ----
__global__ void graph_ptr_kernel(const int* __restrict__ gid, int* __restrict__ gp, int n, int G) {
    int v = blockIdx.x * blockDim.x + threadIdx.x;
    if (v > n) return;
    int g0 = (v == 0) ? -1 : gid[v - 1];
    int g1 = (v == n) ? G  : gid[v];
    for (int g = g0 + 1; g <= g1; g++) gp[g] = v;
}

// ---- fused 32->32 layer, fp16 in/out, half2 BN+accumulate ----
// warp per node; lane = (edge_sub eq = lane>>2, chan_oct cq = lane&3)
// each lane loads 16B = 8 fp16 channels; one warp LDG covers 8 edges.
template <bool BN>
__global__ void __launch_bounds__(512, 2)
gcn_layer32h(const __half* __restrict__ x, const int* __restrict__ rp,
             const int* __restrict__ ci, const float* __restrict__ W,
             const float* __restrict__ bias,
             const double* __restrict__ statsIn,
             const float* __restrict__ gIn, const float* __restrict__ bIn,
             __half* __restrict__ out, int n, double* __restrict__ statsOut) {
    __shared__ float  Ws[32 * 32];
    __shared__ float  bs[32];
    __shared__ float  As[32], Bs[32];
    __shared__ __align__(16) float xv[16][32];
    __shared__ double ssum[32], ssq[32];
    int t = threadIdx.x;
    for (int i = t; i < 1024; i += 512) Ws[i] = W[i];
    if (t < 32) {
        bs[t] = bias[t];
        ssum[t] = 0.0; ssq[t] = 0.0;
        if (BN) {
            double m   = statsIn[t] / (double)n;
            double var = statsIn[32 + t] / (double)n - m * m;
            float  rs  = rsqrtf((float)var + EPS);
            float  A   = gIn[t] * rs;
            As[t] = A;
            Bs[t] = bIn[t] - (float)m * A;
        }
    }
    __syncthreads();
    int w = t >> 5, lane = t & 31;
    int eq = lane >> 2, cq = lane & 3;
    __half2 A2[4], B2[4];
    const __half2 z2 = __floats2half2_rn(0.f, 0.f);
    if (BN) {
#pragma unroll
        for (int k = 0; k < 4; k++) {
            A2[k] = __floats2half2_rn(As[cq * 8 + 2 * k], As[cq * 8 + 2 * k + 1]);
            B2[k] = __floats2half2_rn(Bs[cq * 8 + 2 * k], Bs[cq * 8 + 2 * k + 1]);
        }
    }
    int warpsTotal = gridDim.x * 16;
    int wg = blockIdx.x * 16 + w;
    double dsum = 0.0, dsq = 0.0;
    for (int v = wg; v < n; v += warpsTotal) {
        int beg = __ldg(&rp[v]), end = __ldg(&rp[v + 1]);
        float acc[8];
#pragma unroll
        for (int k = 0; k < 8; k++) acc[k] = 0.f;

        auto accum1 = [&](uint4 u) {
            const unsigned* a = &u.x;
#pragma unroll
            for (int k = 0; k < 4; k++) {
                __half2 p = *(const __half2*)&a[k];
                if (BN) p = __hmax2(__hfma2(p, A2[k], B2[k]), z2);
                float2 f = __half22float2(p);
                acc[2 * k]     += f.x;
                acc[2 * k + 1] += f.y;
            }
        };

        int j = beg;
        for (; j + 16 <= end; j += 16) {
            int s0 = __ldg(&ci[j + eq]);
            int s1 = __ldg(&ci[j + 8 + eq]);
            uint4 u0 = __ldg((const uint4*)(x + (size_t)s0 * 32) + cq);
            uint4 u1 = __ldg((const uint4*)(x + (size_t)s1 * 32) + cq);
            const unsigned* a0 = &u0.x;
            const unsigned* a1 = &u1.x;
#pragma unroll
            for (int k = 0; k < 4; k++) {
                __half2 p0 = *(const __half2*)&a0[k];
                __half2 p1 = *(const __half2*)&a1[k];
                if (BN) {
                    p0 = __hmax2(__hfma2(p0, A2[k], B2[k]), z2);
                    p1 = __hmax2(__hfma2(p1, A2[k], B2[k]), z2);
                }
                float2 f = __half22float2(__hadd2(p0, p1));
                acc[2 * k]     += f.x;
                acc[2 * k + 1] += f.y;
            }
        }
        if (j + 8 <= end) {
            int s0 = __ldg(&ci[j + eq]);
            uint4 u0 = __ldg((const uint4*)(x + (size_t)s0 * 32) + cq);
            accum1(u0);
            j += 8;
        }
        if (j + eq < end) {
            int s0 = __ldg(&ci[j + eq]);
            uint4 u0 = __ldg((const uint4*)(x + (size_t)s0 * 32) + cq);
            accum1(u0);
        }
        // reduce over 8 edge subgroups (lane bits 2,3,4)
#pragma unroll
        for (int k = 0; k < 8; k++) {
            acc[k] += __shfl_xor_sync(0xffffffffu, acc[k], 4);
            acc[k] += __shfl_xor_sync(0xffffffffu, acc[k], 8);
            acc[k] += __shfl_xor_sync(0xffffffffu, acc[k], 16);
        }
        float inv = 1.0f / fmaxf((float)(end - beg), 1.0f);
        if (eq == 0) {
            *(float4*)&xv[w][cq * 8]     = make_float4(acc[0]*inv, acc[1]*inv, acc[2]*inv, acc[3]*inv);
            *(float4*)&xv[w][cq * 8 + 4] = make_float4(acc[4]*inv, acc[5]*inv, acc[6]*inv, acc[7]*inv);
        }
        __syncwarp();
        float o = bs[lane];
#pragma unroll
        for (int i = 0; i < 32; i++) o = fmaf(xv[w][i], Ws[i * 32 + lane], o);
        __syncwarp();
        dsum += (double)o;
        dsq  += (double)o * (double)o;
        float onb = __shfl_xor_sync(0xffffffffu, o, 1);
        if ((lane & 1) == 0) {
            __half2 hv = __floats2half2_rn(o, onb);
            ((__half2*)out)[(size_t)v * 16 + (lane >> 1)] = hv;
        }
    }
    atomicAdd(&ssum[lane], dsum);
    atomicAdd(&ssq[lane],  dsq);
    __syncthreads();
    if (t < 32) {
        atomicAdd(&statsOut[t],      ssum[t]);
        atomicAdd(&statsOut[32 + t], ssq[t]);
    }
}

// ---- fold: z[v] = BN(x3[v]) . W3  (warp per node, lane=channel) ----
__global__ void fold_kernel(const __half* __restrict__ x3,
                            const double* __restrict__ statsIn,
                            const float* __restrict__ gIn, const float* __restrict__ bIn,
                            const float* __restrict__ W3,
                            float* __restrict__ z, int n) {
    __shared__ float As[32], Bs[32], Wsh[32];
    int t = threadIdx.x;
    if (t < 32) {
        double m   = statsIn[t] / (double)n;
        double var = statsIn[32 + t] / (double)n - m * m;
        float  rs  = rsqrtf((float)var + EPS);
        float  A   = gIn[t] * rs;
        As[t] = A;
        Bs[t] = bIn[t] - (float)m * A;
        Wsh[t] = W3[t];
    }
    __syncthreads();
    int w = t >> 5, lane = t & 31;
    int v = blockIdx.x * 8 + w;
    if (v >= n) return;
    float val = __half2float(x3[(size_t)v * 32 + lane]);
    val = fmaxf(fmaf(As[lane], val, Bs[lane]), 0.f) * Wsh[lane];
#pragma unroll
    for (int off = 16; off; off >>= 1) val += __shfl_down_sync(0xffffffffu, val, off);
    if (lane == 0) z[v] = val;
}

// ---- layer 4: scalar mean-gather of z + bias + stats ----
__global__ void __launch_bounds__(512, 2)
layer4_kernel(const float* __restrict__ z, const int* __restrict__ rp,
              const int* __restrict__ ci, const float* __restrict__ b3,
              float* __restrict__ out, int n, double* __restrict__ statsOut) {
    __shared__ double ssum, ssq;
    int t = threadIdx.x;
    if (t == 0) { ssum = 0.0; ssq = 0.0; }
    __syncthreads();
    int w = t >> 5, lane = t & 31;
    int warpsTotal = gridDim.x * 16;
    int wg = blockIdx.x * 16 + w;
    float bias = b3[0];
    double tsum = 0.0, tsq = 0.0;
    for (int v = wg; v < n; v += warpsTotal) {
        int beg = __ldg(&rp[v]), end = __ldg(&rp[v + 1]);
        float s = 0.f;
        for (int j = beg + lane; j < end; j += 32) s += z[__ldg(&ci[j])];
#pragma unroll
        for (int off = 16; off; off >>= 1) s += __shfl_down_sync(0xffffffffu, s, off);
        if (lane == 0) {
            float o = s / fmaxf((float)(end - beg), 1.0f) + bias;
            out[v] = o;
            tsum += (double)o;
            tsq  += (double)o * (double)o;
        }
    }
    if (lane == 0) {
        atomicAdd(&ssum, tsum);
        atomicAdd(&ssq,  tsq);
    }
    __syncthreads();
    if (t == 0) {
        atomicAdd(&statsOut[0],  ssum);
        atomicAdd(&statsOut[32], ssq);
    }
}

// ---- fused per-graph mean pool (BN on the fly; x1..x3 fp16) + MLP head ----
__global__ void pool_mlp_kernel(const float* __restrict__ h,  const __half* __restrict__ x1,
                                const __half* __restrict__ x2, const __half* __restrict__ x3,
                                const float* __restrict__ x4, const int* __restrict__ gp,
                                const double* __restrict__ stats,
                                const float* __restrict__ g0, const float* __restrict__ be0,
                                const float* __restrict__ g1, const float* __restrict__ be1,
                                const float* __restrict__ g2, const float* __restrict__ be2,
                                const float* __restrict__ g3, const float* __restrict__ be3,
                                const float* __restrict__ W0, const float* __restrict__ b0,
                                const float* __restrict__ W1, const float* __restrict__ b1,
                                const float* __restrict__ W2, const float* __restrict__ b2,
                                float* __restrict__ out, int n) {
    __shared__ float As[97], Bs[97];
    __shared__ float hr[129];
    __shared__ float l0[128];
    __shared__ float l1[64];
    int t = threadIdx.x;
    if (t < 97) {
        int layer = (t < 96) ? (t >> 5) : 3;
        int c     = (t < 96) ? (t & 31) : 0;
        const double* st = stats + layer * 64;
        const float* gg = (layer == 0) ? g0 : (layer == 1) ? g1 : (layer == 2) ? g2 : g3;
        const float* bb = (layer == 0) ? be0 : (layer == 1) ? be1 : (layer == 2) ? be2 : be3;
        double m   = st[c] / (double)n;
        double var = st[32 + c] / (double)n - m * m;
        float  rs  = rsqrtf((float)var + EPS);
        float  A   = gg[c] * rs;
        As[t] = A;
        Bs[t] = bb[c] - (float)m * A;
    }
    __syncthreads();
    int g = blockIdx.x;
    int beg = gp[g], end = gp[g + 1];
    float inv = 1.0f / fmaxf((float)(end - beg), 1.0f);
    int w = t >> 5, c = t & 31;
    {
        float s = 0.f;
        if (w == 0) {
            int v = beg;
            for (; v + 4 <= end; v += 4) {
                float a = h[v * 32 + c],       b = h[(v + 1) * 32 + c];
                float d = h[(v + 2) * 32 + c], e = h[(v + 3) * 32 + c];
                s += (a + b) + (d + e);
            }
            for (; v < end; v++) s += h[v * 32 + c];
        } else {
            const __half* p = (w == 1) ? x1 : (w == 2) ? x2 : x3;
            float A = As[(w - 1) * 32 + c];
            float B = Bs[(w - 1) * 32 + c];
            int v = beg;
            for (; v + 4 <= end; v += 4) {
                float a = __half2float(p[(size_t)v * 32 + c]);
                float b = __half2float(p[(size_t)(v + 1) * 32 + c]);
                float d = __half2float(p[(size_t)(v + 2) * 32 + c]);
                float e = __half2float(p[(size_t)(v + 3) * 32 + c]);
                a = fmaxf(fmaf(A, a, B), 0.f); b = fmaxf(fmaf(A, b, B), 0.f);
                d = fmaxf(fmaf(A, d, B), 0.f); e = fmaxf(fmaf(A, e, B), 0.f);
                s += (a + b) + (d + e);
            }
            for (; v < end; v++) s += fmaxf(fmaf(A, __half2float(p[(size_t)v * 32 + c]), B), 0.f);
        }
        hr[t] = s * inv;
    }
    if (t == 0) {
        float A = As[96], B = Bs[96];
        float s = 0.f;
        int v = beg;
        for (; v + 4 <= end; v += 4) {
            float a = fmaxf(fmaf(A, x4[v], B), 0.f);
            float b = fmaxf(fmaf(A, x4[v + 1], B), 0.f);
            float d = fmaxf(fmaf(A, x4[v + 2], B), 0.f);
            float e = fmaxf(fmaf(A, x4[v + 3], B), 0.f);
            s += (a + b) + (d + e);
        }
        for (; v < end; v++) s += fmaxf(fmaf(A, x4[v], B), 0.f);
        hr[128] = s * inv;
    }
    __syncthreads();
    {
        float acc = b0[t];
#pragma unroll 4
        for (int i = 0; i < 129; i++) acc = fmaf(hr[i], W0[i * 128 + t], acc);
        l0[t] = fmaxf(acc, 0.0f);
    }
    __syncthreads();
    if (t < 64) {
        float acc = b1[t];
#pragma unroll 4
        for (int i = 0; i < 128; i++) acc = fmaf(l0[i], W1[i * 64 + t], acc);
        l1[t] = fmaxf(acc, 0.0f);
    }
    __syncthreads();
    if (t == 0) {
        float acc = b2[0];
        for (int i = 0; i < 64; i++) acc = fmaf(l1[i], W2[i], acc);
        out[g] = acc;
    }
}

extern "C" void kernel_launch(void* const* d_in, const int* in_sizes, int n_in,
                              void* d_out, int out_size) {
    const float* h   = (const float*)d_in[0];
    const int*   src = (const int*)d_in[1];
    const int*   dst = (const int*)d_in[2];
    const int*   gid = (const int*)d_in[3];
    const int E = in_sizes[1];
    const int N = in_sizes[3];
    const int G = out_size;
    float* out = (float*)d_out;

    const float* cw[4]; const float* cb[4]; const float* bg[4]; const float* bb[4];
    for (int i = 0; i < 4; i++) {
        cw[i] = (const float*)d_in[4 + 4 * i + 0];
        cb[i] = (const float*)d_in[4 + 4 * i + 1];
        bg[i] = (const float*)d_in[4 + 4 * i + 2];
        bb[i] = (const float*)d_in[4 + 4 * i + 3];
    }
    const float* W0 = (const float*)d_in[20];
    const float* b0 = (const float*)d_in[21];
    const float* W1 = (const float*)d_in[22];
    const float* b1 = (const float*)d_in[23];
    const float* W2 = (const float*)d_in[24];
    const float* b2 = (const float*)d_in[25];

    int *hist, *rp, *pos, *ci, *gp, *tsum;
    __half *h16, *x1, *x2, *x3;
    float *x4, *z;
    double *stats;
    cudaGetSymbolAddress((void**)&hist,  g_hist);
    cudaGetSymbolAddress((void**)&rp,    g_rp);
    cudaGetSymbolAddress((void**)&pos,   g_pos);
    cudaGetSymbolAddress((void**)&ci,    g_ci);
    cudaGetSymbolAddress((void**)&gp,    g_gp);
    cudaGetSymbolAddress((void**)&tsum,  g_tsum);
    cudaGetSymbolAddress((void**)&h16,   g_h16);
    cudaGetSymbolAddress((void**)&x1,    g_x1);
    cudaGetSymbolAddress((void**)&x2,    g_x2);
    cudaGetSymbolAddress((void**)&x3,    g_x3);
    cudaGetSymbolAddress((void**)&x4,    g_x4);
    cudaGetSymbolAddress((void**)&z,     g_z);
    cudaGetSymbolAddress((void**)&stats, g_stats);

    const int T = 256;

    // ---- CSR build + init ----
    cudaMemsetAsync(hist,  0, (size_t)N * sizeof(int));
    cudaMemsetAsync(stats, 0, 4 * 64 * sizeof(double));
    h2half_kernel<<<(N * 32 / 8 + T - 1) / T, T>>>(h, h16, N * 32);
    hist_kernel<<<(E + T - 1) / T, T>>>(dst, hist, E);
    {
        int chunk = (N + SCAN_THREADS - 1) / SCAN_THREADS;
        scan_p1<<<SCAN_THREADS / 256, 256>>>(hist, tsum, N, chunk);
        scan_p2<<<1, 1024>>>(tsum);
        scan_p3<<<SCAN_THREADS / 256, 256>>>(hist, tsum, rp, N, chunk);
    }
    cudaMemcpyAsync(pos, rp, (size_t)N * sizeof(int), cudaMemcpyDeviceToDevice);
    fill_kernel<<<(E + T - 1) / T, T>>>(src, dst, pos, ci, E);
    graph_ptr_kernel<<<(N + 1 + T - 1) / T, T>>>(gid, gp, N, G);

    // ---- GCN layers ----
    const int LG = 296, LT = 512;
    gcn_layer32h<false><<<LG, LT>>>(h16, rp, ci, cw[0], cb[0],
                                    nullptr, nullptr, nullptr,
                                    x1, N, stats + 0 * 64);
    gcn_layer32h<true><<<LG, LT>>>(x1, rp, ci, cw[1], cb[1],
                                   stats + 0 * 64, bg[0], bb[0],
                                   x2, N, stats + 1 * 64);
    gcn_layer32h<true><<<LG, LT>>>(x2, rp, ci, cw[2], cb[2],
                                   stats + 1 * 64, bg[1], bb[1],
                                   x3, N, stats + 2 * 64);
    fold_kernel<<<(N + 7) / 8, 256>>>(x3, stats + 2 * 64, bg[2], bb[2], cw[3], z, N);
    layer4_kernel<<<LG, LT>>>(z, rp, ci, cb[3], x4, N, stats + 3 * 64);

    // ---- fused pool + MLP ----
    pool_mlp_kernel<<<G, 128>>>(h, x1, x2, x3, x4, gp, stats,
                                bg[0], bb[0], bg[1], bb[1], bg[2], bb[2], bg[3], bb[3],
                                W0, b0, W1, b1, W2, b2, out, N);
}